// round 13
// baseline (speedup 1.0000x reference)
#include <cuda_runtime.h>
#include <cuda_bf16.h>
#include <cstdint>
#include <math.h>

#define B_   16
#define C_   256
#define HW_  1024
#define HEADS_ 4
#define DH_  64
#define GROUPS_ 32
#define CPG_ 8
#define EPS_ 1e-6f
#define RS2_ 0.70710678118654752440f
#define QSCALE_ (1.0f/16.0f)

typedef __nv_bfloat16 bf16;

// ---------------- scratch ----------------
__device__ bf16  g_q [B_*HW_*C_];   // pre-scaled by 1/16
__device__ bf16  g_k [B_*HW_*C_];
__device__ bf16  g_h [B_*HW_*C_];
__device__ bf16  g_wt[4*C_*C_];     // W^T: [z][cout][cin]
__device__ bf16  g_vt[B_*HEADS_*DH_*HW_]; // V^T per (b,h): [d][token]
__device__ float g_stat[B_*GROUPS_*2];    // mean, rinv per (b,group)

// ---------------- helpers ----------------
__device__ __forceinline__ uint32_t pk2(float lo, float hi){
    uint32_t d;
    asm("cvt.rn.bf16x2.f32 %0, %1, %2;" : "=r"(d) : "f"(hi), "f"(lo));
    return d;
}
__device__ __forceinline__ void mma16(float* c, uint32_t a0, uint32_t a1,
                                      uint32_t a2, uint32_t a3,
                                      uint32_t b0, uint32_t b1){
    asm volatile("mma.sync.aligned.m16n8k16.row.col.f32.bf16.bf16.f32 "
        "{%0,%1,%2,%3}, {%4,%5,%6,%7}, {%8,%9}, {%0,%1,%2,%3};"
        : "+f"(c[0]), "+f"(c[1]), "+f"(c[2]), "+f"(c[3])
        : "r"(a0), "r"(a1), "r"(a2), "r"(a3), "r"(b0), "r"(b1));
}
__device__ __forceinline__ void ldsm4(uint32_t& r0, uint32_t& r1,
                                      uint32_t& r2, uint32_t& r3, uint32_t a){
    asm volatile("ldmatrix.sync.aligned.m8n8.x4.shared.b16 {%0,%1,%2,%3}, [%4];"
        : "=r"(r0), "=r"(r1), "=r"(r2), "=r"(r3) : "r"(a));
}
__device__ __forceinline__ uint32_t su32(const void* p){
    return (uint32_t)__cvta_generic_to_shared(p);
}
#define CPA16(s, g) asm volatile("cp.async.cg.shared.global [%0], [%1], 16;" :: "r"(s), "l"(g))
#define CP_COMMIT() asm volatile("cp.async.commit_group;" ::: "memory")
#define CP_WAIT0()  asm volatile("cp.async.wait_group 0;" ::: "memory")

// ---------------- Kernel 1: GroupNorm stats only ----------------
__global__ __launch_bounds__(256) void stats_kernel(const float* __restrict__ x)
{
    __shared__ float red[64];
    int tid = threadIdx.x;
    const float* base = x + (size_t)blockIdx.x*CPG_*HW_;
    float s = 0.f, sq = 0.f;
    #pragma unroll
    for (int i = 0; i < 8; i++) {
        float4 v = *(const float4*)&base[(tid + i*256)*4];
        s  += v.x + v.y + v.z + v.w;
        sq += v.x*v.x + v.y*v.y + v.z*v.z + v.w*v.w;
    }
    #pragma unroll
    for (int o = 16; o; o >>= 1) {
        s  += __shfl_xor_sync(0xffffffffu, s,  o);
        sq += __shfl_xor_sync(0xffffffffu, sq, o);
    }
    int w = tid >> 5;
    if ((tid & 31) == 0) { red[w] = s; red[32+w] = sq; }
    __syncthreads();
    if (tid == 0) {
        s = 0.f; sq = 0.f;
        #pragma unroll
        for (int i = 0; i < 8; i++) { s += red[i]; sq += red[32+i]; }
        float mean = s * (1.f/8192.f);
        float var  = sq * (1.f/8192.f) - mean*mean;
        g_stat[blockIdx.x*2]   = mean;
        g_stat[blockIdx.x*2+1] = rsqrtf(var + EPS_);
    }
}

// ---------------- Kernel 2: weight transpose -> bf16 [cout][cin] ----------
__global__ void wt_kernel(const float* __restrict__ Wq, const float* __restrict__ Wk,
                          const float* __restrict__ Wv, const float* __restrict__ Wp)
{
    __shared__ float t[32][33];
    int z = blockIdx.z;
    const float* W = (z==0)?Wq:(z==1)?Wk:(z==2)?Wv:Wp;
    bf16* WT = g_wt + (size_t)z*C_*C_;
    int x0 = blockIdx.x*32, y0 = blockIdx.y*32;
    int tx = threadIdx.x, ty = threadIdx.y;
    #pragma unroll
    for (int i = 0; i < 4; i++)
        t[ty+8*i][tx] = W[(size_t)(y0+ty+8*i)*C_ + x0+tx];
    __syncthreads();
    #pragma unroll
    for (int i = 0; i < 4; i++)
        WT[(size_t)(x0+ty+8*i)*C_ + y0+tx] = __float2bfloat16_rn(t[tx][ty+8*i]);
}

// ---------------- Kernel 3: fused GN + QKV + V-transpose epilogue ----------
#define SAE 40
#define SBE 40
// smem: sA 128*40 + sB 3*64*40 = 12800 bf16 (25600 B) + sXf 32*133 f32 (17024 B) = 42624 B
__global__ __launch_bounds__(256) void qkv_kernel(
    const float* __restrict__ x,  const float* __restrict__ gns,
    const float* __restrict__ gnb,
    const float* __restrict__ bq, const float* __restrict__ bk,
    const float* __restrict__ bv)
{
    extern __shared__ bf16 smb[];
    bf16* sA  = smb;                    // [128][SAE]
    bf16* sB0 = sA  + 128*SAE;          // [64][SBE] x3
    bf16* sB1 = sB0 + 64*SBE;
    bf16* sB2 = sB1 + 64*SBE;
    float* sXf = (float*)(smb + 128*SAE + 3*64*SBE);  // [32][133]
    int d0 = blockIdx.x*64, m0 = blockIdx.y*128;
    int btok = m0 >> 10, n0 = m0 & 1023;
    int tid = threadIdx.x, wid = tid>>5, lane = tid&31;
    int g = lane>>2, t = lane&3;
    int m0w = (wid>>1)*32, n0w = (wid&1)*32;

    int r8 = lane&7, mlo = (lane>>3)&1, mhi = lane>>4;
    uint32_t aB  = su32(sA)  + (uint32_t)((m0w + r8 + mlo*8)*SAE + mhi*8)*2;
    uint32_t bB0 = su32(sB0) + (uint32_t)((n0w + r8 + mhi*8)*SBE + mlo*8)*2;
    uint32_t bB1 = su32(sB1) + (uint32_t)((n0w + r8 + mhi*8)*SBE + mlo*8)*2;
    uint32_t bB2 = su32(sB2) + (uint32_t)((n0w + r8 + mhi*8)*SBE + mlo*8)*2;

    float acc[3][2][4][4];
    #pragma unroll
    for (int z = 0; z < 3; z++)
        #pragma unroll
        for (int mt = 0; mt < 2; mt++)
            #pragma unroll
            for (int nt = 0; nt < 4; nt++)
                #pragma unroll
                for (int i = 0; i < 4; i++) acc[z][mt][nt][i] = 0.f;

    for (int kc = 0; kc < 8; kc++) {
        int k0 = kc*32;
        __syncthreads();
        // phase 1: x (channel-major) -> normalized fp32 tile sXf[c][tok]
        #pragma unroll
        for (int i = 0; i < 4; i++) {
            int idx = tid + i*256;
            int c = idx>>5, tq = (idx&31)*4;
            int ch = k0 + c;
            int bg = btok*32 + (ch>>3);
            float mean = g_stat[bg*2], rinv = g_stat[bg*2+1];
            float aa = rinv * gns[ch];
            float bb = gnb[ch] - mean*aa;
            float4 v = *(const float4*)&x[((size_t)btok*C_ + ch)*HW_ + n0 + tq];
            // scalar stores: row stride 133 floats is not 16B-aligned
            sXf[c*133 + tq]     = v.x*aa + bb;
            sXf[c*133 + tq + 1] = v.y*aa + bb;
            sXf[c*133 + tq + 2] = v.z*aa + bb;
            sXf[c*133 + tq + 3] = v.w*aa + bb;
        }
        {   // B tiles: 64n x 32k each
            int n = tid>>2, seg = (tid&3)*8;
            size_t off = (size_t)(d0+n)*C_ + k0 + seg;
            *(uint4*)&sB0[n*SBE + seg] = *(const uint4*)&g_wt[off];
            *(uint4*)&sB1[n*SBE + seg] = *(const uint4*)&g_wt[C_*C_ + off];
            *(uint4*)&sB2[n*SBE + seg] = *(const uint4*)&g_wt[2*C_*C_ + off];
        }
        __syncthreads();
        // phase 2: transpose sXf -> sA bf16 [tok][c]
        #pragma unroll
        for (int i = 0; i < 2; i++) {
            int idx = tid + i*256;
            int row = idx>>2, cq = (idx&3)*8;
            bf16 tmp[8];
            #pragma unroll
            for (int j = 0; j < 8; j++)
                tmp[j] = __float2bfloat16_rn(sXf[(cq+j)*133 + row]);
            *(uint4*)&sA[row*SAE + cq] = *(uint4*)tmp;
        }
        __syncthreads();
        #pragma unroll
        for (int s = 0; s < 2; s++) {
            uint32_t a[2][4];
            #pragma unroll
            for (int mt = 0; mt < 2; mt++)
                ldsm4(a[mt][0], a[mt][1], a[mt][2], a[mt][3],
                      aB + (uint32_t)(mt*16*SAE + s*16)*2);
            #pragma unroll
            for (int z = 0; z < 3; z++) {
                uint32_t bb = (z==0)?bB0:(z==1)?bB1:bB2;
                #pragma unroll
                for (int nt2 = 0; nt2 < 2; nt2++) {
                    uint32_t b0,b1,c0,c1;
                    ldsm4(b0,b1,c0,c1, bb + (uint32_t)(nt2*16*SBE + s*16)*2);
                    #pragma unroll
                    for (int mt = 0; mt < 2; mt++) {
                        mma16(acc[z][mt][2*nt2],   a[mt][0],a[mt][1],a[mt][2],a[mt][3], b0, b1);
                        mma16(acc[z][mt][2*nt2+1], a[mt][0],a[mt][1],a[mt][2],a[mt][3], c0, c1);
                    }
                }
            }
        }
    }

    #pragma unroll
    for (int z = 0; z < 2; z++) {
        const float* bias = (z==0)?bq:bk;
        bf16* out = (z==0)?g_q:g_k;
        float scl = (z==0)?QSCALE_:1.f;
        #pragma unroll
        for (int mt = 0; mt < 2; mt++) {
            int r = m0 + m0w + mt*16 + g;
            #pragma unroll
            for (int nt = 0; nt < 4; nt++) {
                int c = d0 + n0w + nt*8 + 2*t;
                float b0v = bias[c], b1v = bias[c+1];
                *(uint32_t*)&out[(size_t)r*C_ + c] =
                    pk2((acc[z][mt][nt][0]+b0v)*scl, (acc[z][mt][nt][1]+b1v)*scl);
                *(uint32_t*)&out[(size_t)(r+8)*C_ + c] =
                    pk2((acc[z][mt][nt][2]+b0v)*scl, (acc[z][mt][nt][3]+b1v)*scl);
            }
        }
    }

    __syncthreads();
    {
        bf16* sT = smb;                 // [64][136]
        #pragma unroll
        for (int mt = 0; mt < 2; mt++) {
            int r = m0w + mt*16 + g;
            #pragma unroll
            for (int nt = 0; nt < 4; nt++) {
                int c = n0w + nt*8 + 2*t;
                float b0v = bv[d0 + c], b1v = bv[d0 + c + 1];
                sT[c*136 + r]         = __float2bfloat16_rn(acc[2][mt][nt][0] + b0v);
                sT[(c+1)*136 + r]     = __float2bfloat16_rn(acc[2][mt][nt][1] + b1v);
                sT[c*136 + r + 8]     = __float2bfloat16_rn(acc[2][mt][nt][2] + b0v);
                sT[(c+1)*136 + r + 8] = __float2bfloat16_rn(acc[2][mt][nt][3] + b1v);
            }
        }
        __syncthreads();
        int bh = btok*4 + (d0 >> 6);
        bf16* dst = g_vt + (size_t)bh*DH_*HW_;
        #pragma unroll
        for (int i = 0; i < 4; i++) {
            int idx = tid + i*256, d = idx>>4, ch = (idx&15)*8;
            *(uint4*)&dst[(size_t)d*HW_ + n0 + ch] = *(uint4*)&sT[d*136 + ch];
        }
    }
}

// ---------------- Kernel 4: attention, 4 warps x 32 q-rows, cp.async ------
#define SQst 72
// smem elems: Q 128*72=9216, K/V double buf: 4*64*72=18432 -> 27648 (55296 B)
__global__ __launch_bounds__(128,3) void attn_kernel()
{
    extern __shared__ bf16 smb[];
    bf16* sQ = smb;                          // [128][SQst]
    bf16* sK[2] = { smb +  9216, smb + 18432 };
    bf16* sV[2] = { smb + 13824, smb + 23040 };
    int q0 = blockIdx.x*128;
    int bh = blockIdx.y, b = bh>>2, h = bh&3;
    size_t base = (size_t)b*HW_*C_ + (size_t)h*DH_;
    const bf16* vtb = g_vt + (size_t)bh*DH_*HW_;
    int tid = threadIdx.x, wid = tid>>5, lane = tid&31;

    int r8 = lane&7, mlo = (lane>>3)&1, mhi = lane>>4;
    uint32_t qB = su32(sQ) + (uint32_t)((wid*32 + r8 + mlo*8)*SQst + mhi*8)*2;
    uint32_t kB[2], vB[2];
    #pragma unroll
    for (int i = 0; i < 2; i++) {
        kB[i] = su32(sK[i]) + (uint32_t)((r8 + mhi*8)*SQst + mlo*8)*2;
        vB[i] = su32(sV[i]) + (uint32_t)((r8 + mhi*8)*SQst + mlo*8)*2;
    }

    // stage Q (128x64 = 1024 uint4): 8 per thread
    #pragma unroll
    for (int i = 0; i < 8; i++) {
        int f = tid + i*128, row = f>>3, seg = (f&7)*8;
        *(uint4*)&sQ[row*SQst + seg] =
            *(const uint4*)&g_q[base + (size_t)(q0+row)*C_ + seg];
    }
    auto ldtile = [&](int kt, int bb){
        #pragma unroll
        for (int i = 0; i < 4; i++) {
            int f = tid + i*128, row = f>>3, seg = (f&7)*8;
            CPA16(su32(&sK[bb][row*SQst + seg]),
                  &g_k[base + (size_t)(kt*64 + row)*C_ + seg]);
            CPA16(su32(&sV[bb][row*SQst + seg]),
                  &vtb[(size_t)row*HW_ + kt*64 + seg]);
        }
    };
    ldtile(0, 0); CP_COMMIT();

    __syncthreads();
    uint32_t aQ[2][4][4];
    #pragma unroll
    for (int mt = 0; mt < 2; mt++)
        #pragma unroll
        for (int k4 = 0; k4 < 4; k4++)
            ldsm4(aQ[mt][k4][0], aQ[mt][k4][1], aQ[mt][k4][2], aQ[mt][k4][3],
                  qB + (uint32_t)(mt*16*SQst + k4*16)*2);

    float o[2][8][4];
    #pragma unroll
    for (int mt = 0; mt < 2; mt++)
        #pragma unroll
        for (int nt = 0; nt < 8; nt++)
            #pragma unroll
            for (int i = 0; i < 4; i++) o[mt][nt][i] = 0.f;
    float lp[2][2] = {{0.f,0.f},{0.f,0.f}};

    for (int kt = 0; kt < 16; kt++) {
        int bb = kt & 1;
        CP_WAIT0();
        __syncthreads();
        if (kt < 15) { ldtile(kt+1, bb^1); CP_COMMIT(); }

        #pragma unroll
        for (int s = 0; s < 4; s++) {
            float S[2][2][4] = {};
            #pragma unroll
            for (int k4 = 0; k4 < 4; k4++) {
                uint32_t b0,b1,c0,c1;
                ldsm4(b0,b1,c0,c1, kB[bb] + (uint32_t)(s*16*SQst + k4*16)*2);
                #pragma unroll
                for (int mt = 0; mt < 2; mt++) {
                    mma16(S[mt][0], aQ[mt][k4][0],aQ[mt][k4][1],aQ[mt][k4][2],aQ[mt][k4][3], b0, b1);
                    mma16(S[mt][1], aQ[mt][k4][0],aQ[mt][k4][1],aQ[mt][k4][2],aQ[mt][k4][3], c0, c1);
                }
            }
            uint32_t p[2][4];
            #pragma unroll
            for (int mt = 0; mt < 2; mt++) {
                float e00 = __expf(S[mt][0][0]), e01 = __expf(S[mt][0][1]);
                float e02 = __expf(S[mt][0][2]), e03 = __expf(S[mt][0][3]);
                float e10 = __expf(S[mt][1][0]), e11 = __expf(S[mt][1][1]);
                float e12 = __expf(S[mt][1][2]), e13 = __expf(S[mt][1][3]);
                lp[mt][0] += e00 + e01 + e10 + e11;
                lp[mt][1] += e02 + e03 + e12 + e13;
                p[mt][0] = pk2(e00, e01);
                p[mt][1] = pk2(e02, e03);
                p[mt][2] = pk2(e10, e11);
                p[mt][3] = pk2(e12, e13);
            }
            #pragma unroll
            for (int nt2 = 0; nt2 < 4; nt2++) {
                uint32_t b0,b1,c0,c1;
                ldsm4(b0,b1,c0,c1, vB[bb] + (uint32_t)(nt2*16*SQst + s*16)*2);
                #pragma unroll
                for (int mt = 0; mt < 2; mt++) {
                    mma16(o[mt][2*nt2],   p[mt][0],p[mt][1],p[mt][2],p[mt][3], b0, b1);
                    mma16(o[mt][2*nt2+1], p[mt][0],p[mt][1],p[mt][2],p[mt][3], c0, c1);
                }
            }
        }
    }

    int g = lane>>2, t = lane&3;
    #pragma unroll
    for (int mt = 0; mt < 2; mt++) {
        lp[mt][0] += __shfl_xor_sync(0xffffffffu, lp[mt][0], 1);
        lp[mt][0] += __shfl_xor_sync(0xffffffffu, lp[mt][0], 2);
        lp[mt][1] += __shfl_xor_sync(0xffffffffu, lp[mt][1], 1);
        lp[mt][1] += __shfl_xor_sync(0xffffffffu, lp[mt][1], 2);
        float inv0 = 1.f / lp[mt][0], inv1 = 1.f / lp[mt][1];
        int row = q0 + wid*32 + mt*16 + g;
        #pragma unroll
        for (int nt = 0; nt < 8; nt++) {
            int c = nt*8 + 2*t;
            *(uint32_t*)&g_h[base + (size_t)row*C_ + c] =
                pk2(o[mt][nt][0]*inv0, o[mt][nt][1]*inv0);
            *(uint32_t*)&g_h[base + (size_t)(row+8)*C_ + c] =
                pk2(o[mt][nt][2]*inv1, o[mt][nt][3]*inv1);
        }
    }
}

// ---------------- Kernel 5: proj + bias + residual (coalesced epilogue) ----
// smem: max(sA+sB = 15360 B, sOut 64*132*4 = 33792 B) -> 33792 B
__global__ __launch_bounds__(256) void proj_kernel(
    const float* __restrict__ bp, const float* __restrict__ x,
    float* __restrict__ out)
{
    extern __shared__ bf16 smb[];
    bf16* sA = smb;                 // [128][SAE]
    bf16* sB = sA + 128*SAE;        // [64][SBE]
    const bf16* WT = g_wt + (size_t)3*C_*C_;
    int d0 = blockIdx.x*64, m0 = blockIdx.y*128;
    int tid = threadIdx.x, wid = tid>>5, lane = tid&31;
    int g = lane>>2, t = lane&3;
    int m0w = (wid>>1)*32, n0w = (wid&1)*32;

    int r8 = lane&7, mlo = (lane>>3)&1, mhi = lane>>4;
    uint32_t aB = su32(sA) + (uint32_t)((m0w + r8 + mlo*8)*SAE + mhi*8)*2;
    uint32_t bB = su32(sB) + (uint32_t)((n0w + r8 + mhi*8)*SBE + mlo*8)*2;

    float acc[2][4][4];
    #pragma unroll
    for (int mt = 0; mt < 2; mt++)
        #pragma unroll
        for (int nt = 0; nt < 4; nt++)
            #pragma unroll
            for (int i = 0; i < 4; i++) acc[mt][nt][i] = 0.f;

    for (int kc = 0; kc < 8; kc++) {
        int k0 = kc*32;
        __syncthreads();
        #pragma unroll
        for (int i = 0; i < 2; i++) {
            int f = tid + i*256, row = f>>2, seg = (f&3)*8;
            *(uint4*)&sA[row*SAE + seg] =
                *(const uint4*)&g_h[(size_t)(m0+row)*C_ + k0 + seg];
        }
        {
            int n = tid>>2, seg = (tid&3)*8;
            *(uint4*)&sB[n*SBE + seg] =
                *(const uint4*)&WT[(size_t)(d0+n)*C_ + k0 + seg];
        }
        __syncthreads();
        #pragma unroll
        for (int s = 0; s < 2; s++) {
            uint32_t a[2][4];
            #pragma unroll
            for (int mt = 0; mt < 2; mt++)
                ldsm4(a[mt][0], a[mt][1], a[mt][2], a[mt][3],
                      aB + (uint32_t)(mt*16*SAE + s*16)*2);
            #pragma unroll
            for (int nt2 = 0; nt2 < 2; nt2++) {
                uint32_t b0,b1,c0,c1;
                ldsm4(b0,b1,c0,c1, bB + (uint32_t)(nt2*16*SBE + s*16)*2);
                #pragma unroll
                for (int mt = 0; mt < 2; mt++) {
                    mma16(acc[mt][2*nt2],   a[mt][0],a[mt][1],a[mt][2],a[mt][3], b0, b1);
                    mma16(acc[mt][2*nt2+1], a[mt][0],a[mt][1],a[mt][2],a[mt][3], c0, c1);
                }
            }
        }
    }

    // stage acc+bias into smem [d_local 64][tok_local 128] then coalesced out
    __syncthreads();
    float* sOut = (float*)smb;      // [64][132] (528B rows, 16B aligned)
    #pragma unroll
    for (int mt = 0; mt < 2; mt++) {
        #pragma unroll
        for (int rh = 0; rh < 2; rh++) {
            int rl = m0w + mt*16 + g + rh*8;
            #pragma unroll
            for (int nt = 0; nt < 4; nt++) {
                int dl = n0w + nt*8 + 2*t;
                sOut[dl*132 + rl]     = acc[mt][nt][rh*2+0] + bp[d0+dl];
                sOut[(dl+1)*132 + rl] = acc[mt][nt][rh*2+1] + bp[d0+dl+1];
            }
        }
    }
    __syncthreads();
    int btok = m0 >> 10, n0 = m0 & 1023;
    #pragma unroll
    for (int i = 0; i < 8; i++) {
        int idx = tid + i*256;
        int d = idx>>5, tq = (idx&31)*4;
        float4 v = *(float4*)&sOut[d*132 + tq];
        size_t gi = ((size_t)btok*C_ + d0 + d)*HW_ + n0 + tq;
        float4 xv = *(const float4*)&x[gi];
        v.x = (v.x + xv.x)*RS2_; v.y = (v.y + xv.y)*RS2_;
        v.z = (v.z + xv.z)*RS2_; v.w = (v.w + xv.w)*RS2_;
        *(float4*)&out[gi] = v;
    }
}

// ---------------------------------------------------------------------------
extern "C" void kernel_launch(void* const* d_in, const int* in_sizes, int n_in,
                              void* d_out, int out_size)
{
    const float* x   = (const float*)d_in[0];
    const float* gns = (const float*)d_in[1];
    const float* gnb = (const float*)d_in[2];
    const float* Wq  = (const float*)d_in[3];
    const float* bq  = (const float*)d_in[4];
    const float* Wk  = (const float*)d_in[5];
    const float* bk  = (const float*)d_in[6];
    const float* Wv  = (const float*)d_in[7];
    const float* bv  = (const float*)d_in[8];
    const float* Wp  = (const float*)d_in[9];
    const float* bp  = (const float*)d_in[10];
    float* out = (float*)d_out;

    const int smem_qkv  = (128*SAE + 3*64*SBE)*2 + 32*133*4;  // 42624 B
    const int smem_attn = 27648 * 2;                          // 55296 B
    const int smem_proj = 64*132*4;                           // 33792 B

    cudaFuncSetAttribute(attn_kernel,
                         cudaFuncAttributeMaxDynamicSharedMemorySize, smem_attn);

    stats_kernel<<<B_*GROUPS_, 256>>>(x);
    wt_kernel  <<<dim3(8,8,4), dim3(32,8)>>>(Wq, Wk, Wv, Wp);
    qkv_kernel <<<dim3(4, 128), 256, smem_qkv>>>(x, gns, gnb, bq, bk, bv);
    attn_kernel<<<dim3(8, 64), 128, smem_attn>>>();
    proj_kernel<<<dim3(4, 128), 256, smem_proj>>>(bp, x, out);
}

// round 14
// speedup vs baseline: 1.0519x; 1.0519x over previous
#include <cuda_runtime.h>
#include <cuda_bf16.h>
#include <cstdint>
#include <math.h>

#define B_   16
#define C_   256
#define HW_  1024
#define HEADS_ 4
#define DH_  64
#define GROUPS_ 32
#define CPG_ 8
#define EPS_ 1e-6f
#define RS2_ 0.70710678118654752440f
#define QSCALE_ (1.0f/16.0f)

typedef __nv_bfloat16 bf16;

// ---------------- scratch ----------------
__device__ bf16 g_xn[B_*HW_*C_];
__device__ bf16 g_q [B_*HW_*C_];   // pre-scaled by 1/16
__device__ bf16 g_k [B_*HW_*C_];
__device__ bf16 g_h [B_*HW_*C_];
__device__ bf16 g_wt[4*C_*C_];     // W^T: [z][cout][cin]
__device__ bf16 g_vt[B_*HEADS_*DH_*HW_]; // V^T per (b,h): [d][token]

// ---------------- helpers ----------------
__device__ __forceinline__ uint32_t pk2(float lo, float hi){
    uint32_t d;
    asm("cvt.rn.bf16x2.f32 %0, %1, %2;" : "=r"(d) : "f"(hi), "f"(lo));
    return d;
}
__device__ __forceinline__ void mma16(float* c, uint32_t a0, uint32_t a1,
                                      uint32_t a2, uint32_t a3,
                                      uint32_t b0, uint32_t b1){
    asm volatile("mma.sync.aligned.m16n8k16.row.col.f32.bf16.bf16.f32 "
        "{%0,%1,%2,%3}, {%4,%5,%6,%7}, {%8,%9}, {%0,%1,%2,%3};"
        : "+f"(c[0]), "+f"(c[1]), "+f"(c[2]), "+f"(c[3])
        : "r"(a0), "r"(a1), "r"(a2), "r"(a3), "r"(b0), "r"(b1));
}
__device__ __forceinline__ void ldsm4(uint32_t& r0, uint32_t& r1,
                                      uint32_t& r2, uint32_t& r3, uint32_t a){
    asm volatile("ldmatrix.sync.aligned.m8n8.x4.shared.b16 {%0,%1,%2,%3}, [%4];"
        : "=r"(r0), "=r"(r1), "=r"(r2), "=r"(r3) : "r"(a));
}
__device__ __forceinline__ uint32_t su32(const void* p){
    return (uint32_t)__cvta_generic_to_shared(p);
}
#define CPA16(s, g) asm volatile("cp.async.cg.shared.global [%0], [%1], 16;" :: "r"(s), "l"(g))
#define CP_COMMIT() asm volatile("cp.async.commit_group;" ::: "memory")
#define CP_WAIT0()  asm volatile("cp.async.wait_group 0;" ::: "memory")

// ---------------- Kernel 1: GroupNorm -> (B,N,C) bf16 ----------------
__global__ __launch_bounds__(256) void gn_kernel(
    const float* __restrict__ x, const float* __restrict__ sc,
    const float* __restrict__ bi)
{
    __shared__ float xs[CPG_*HW_];
    __shared__ float red[64];
    int b = blockIdx.x >> 5, g = blockIdx.x & 31;
    const float* base = x + (size_t)b*C_*HW_ + (size_t)g*CPG_*HW_;
    int tid = threadIdx.x;
    float s = 0.f, sq = 0.f;
    #pragma unroll 8
    for (int i = tid; i < CPG_*HW_; i += 256) {
        float v = base[i]; xs[i] = v; s += v; sq += v*v;
    }
    #pragma unroll
    for (int o = 16; o; o >>= 1) {
        s  += __shfl_xor_sync(0xffffffffu, s,  o);
        sq += __shfl_xor_sync(0xffffffffu, sq, o);
    }
    int w = tid >> 5;
    if ((tid & 31) == 0) { red[w] = s; red[32+w] = sq; }
    __syncthreads();
    if (tid < 32) {
        s  = (tid < 8) ? red[tid]    : 0.f;
        sq = (tid < 8) ? red[32+tid] : 0.f;
        #pragma unroll
        for (int o = 4; o; o >>= 1) {
            s  += __shfl_xor_sync(0xffffffffu, s,  o);
            sq += __shfl_xor_sync(0xffffffffu, sq, o);
        }
        if (tid == 0) { red[0] = s; red[1] = sq; }
    }
    __syncthreads();
    float mean = red[0] * (1.f/8192.f);
    float var  = red[1] * (1.f/8192.f) - mean*mean;
    float rinv = rsqrtf(var + EPS_);
    float scs[CPG_], bis[CPG_];
    #pragma unroll
    for (int c = 0; c < CPG_; c++) { scs[c] = sc[g*CPG_+c]; bis[c] = bi[g*CPG_+c]; }
    for (int n = tid; n < HW_; n += 256) {
        float buf[CPG_];
        #pragma unroll
        for (int c = 0; c < CPG_; c++)
            buf[c] = (xs[c*HW_+n] - mean)*rinv*scs[c] + bis[c];
        uint4 u;
        u.x = pk2(buf[0],buf[1]); u.y = pk2(buf[2],buf[3]);
        u.z = pk2(buf[4],buf[5]); u.w = pk2(buf[6],buf[7]);
        *(uint4*)&g_xn[((size_t)(b*HW_+n))*C_ + g*CPG_] = u;
    }
}

// ---------------- Kernel 2: weight transpose -> bf16 [cout][cin] ----------
__global__ void wt_kernel(const float* __restrict__ Wq, const float* __restrict__ Wk,
                          const float* __restrict__ Wv, const float* __restrict__ Wp)
{
    __shared__ float t[32][33];
    int z = blockIdx.z;
    const float* W = (z==0)?Wq:(z==1)?Wk:(z==2)?Wv:Wp;
    bf16* WT = g_wt + (size_t)z*C_*C_;
    int x0 = blockIdx.x*32, y0 = blockIdx.y*32;
    int tx = threadIdx.x, ty = threadIdx.y;
    #pragma unroll
    for (int i = 0; i < 4; i++)
        t[ty+8*i][tx] = W[(size_t)(y0+ty+8*i)*C_ + x0+tx];
    __syncthreads();
    #pragma unroll
    for (int i = 0; i < 4; i++)
        WT[(size_t)(x0+ty+8*i)*C_ + y0+tx] = __float2bfloat16_rn(t[tx][ty+8*i]);
}

// ---------------- Kernel 3: fused QKV + V-transpose epilogue ----------------
#define SAE 40
#define SBE 40
__global__ __launch_bounds__(256) void qkv_kernel(
    const float* __restrict__ bq, const float* __restrict__ bk,
    const float* __restrict__ bv)
{
    extern __shared__ bf16 smb[];
    bf16* sA  = smb;                    // [128][SAE]
    bf16* sB0 = sA  + 128*SAE;          // [64][SBE] x3
    bf16* sB1 = sB0 + 64*SBE;
    bf16* sB2 = sB1 + 64*SBE;
    int d0 = blockIdx.x*64, m0 = blockIdx.y*128;
    int tid = threadIdx.x, wid = tid>>5, lane = tid&31;
    int g = lane>>2, t = lane&3;
    int m0w = (wid>>1)*32, n0w = (wid&1)*32;

    int r8 = lane&7, mlo = (lane>>3)&1, mhi = lane>>4;
    uint32_t aB  = su32(sA)  + (uint32_t)((m0w + r8 + mlo*8)*SAE + mhi*8)*2;
    uint32_t bB0 = su32(sB0) + (uint32_t)((n0w + r8 + mhi*8)*SBE + mlo*8)*2;
    uint32_t bB1 = su32(sB1) + (uint32_t)((n0w + r8 + mhi*8)*SBE + mlo*8)*2;
    uint32_t bB2 = su32(sB2) + (uint32_t)((n0w + r8 + mhi*8)*SBE + mlo*8)*2;

    float acc[3][2][4][4];
    #pragma unroll
    for (int z = 0; z < 3; z++)
        #pragma unroll
        for (int mt = 0; mt < 2; mt++)
            #pragma unroll
            for (int nt = 0; nt < 4; nt++)
                #pragma unroll
                for (int i = 0; i < 4; i++) acc[z][mt][nt][i] = 0.f;

    for (int kc = 0; kc < 8; kc++) {
        int k0 = kc*32;
        __syncthreads();
        #pragma unroll
        for (int i = 0; i < 2; i++) {
            int f = tid + i*256;
            int row = f>>2, seg = (f&3)*8;
            *(uint4*)&sA[row*SAE + seg] =
                *(const uint4*)&g_xn[(size_t)(m0+row)*C_ + k0 + seg];
        }
        {
            int n = tid>>2, seg = (tid&3)*8;
            size_t off = (size_t)(d0+n)*C_ + k0 + seg;
            *(uint4*)&sB0[n*SBE + seg] = *(const uint4*)&g_wt[off];
            *(uint4*)&sB1[n*SBE + seg] = *(const uint4*)&g_wt[C_*C_ + off];
            *(uint4*)&sB2[n*SBE + seg] = *(const uint4*)&g_wt[2*C_*C_ + off];
        }
        __syncthreads();
        #pragma unroll
        for (int s = 0; s < 2; s++) {
            uint32_t a[2][4];
            #pragma unroll
            for (int mt = 0; mt < 2; mt++)
                ldsm4(a[mt][0], a[mt][1], a[mt][2], a[mt][3],
                      aB + (uint32_t)(mt*16*SAE + s*16)*2);
            #pragma unroll
            for (int z = 0; z < 3; z++) {
                uint32_t bb = (z==0)?bB0:(z==1)?bB1:bB2;
                #pragma unroll
                for (int nt2 = 0; nt2 < 2; nt2++) {
                    uint32_t b0,b1,c0,c1;
                    ldsm4(b0,b1,c0,c1, bb + (uint32_t)(nt2*16*SBE + s*16)*2);
                    #pragma unroll
                    for (int mt = 0; mt < 2; mt++) {
                        mma16(acc[z][mt][2*nt2],   a[mt][0],a[mt][1],a[mt][2],a[mt][3], b0, b1);
                        mma16(acc[z][mt][2*nt2+1], a[mt][0],a[mt][1],a[mt][2],a[mt][3], c0, c1);
                    }
                }
            }
        }
    }

    #pragma unroll
    for (int z = 0; z < 2; z++) {
        const float* bias = (z==0)?bq:bk;
        bf16* out = (z==0)?g_q:g_k;
        float scl = (z==0)?QSCALE_:1.f;
        #pragma unroll
        for (int mt = 0; mt < 2; mt++) {
            int r = m0 + m0w + mt*16 + g;
            #pragma unroll
            for (int nt = 0; nt < 4; nt++) {
                int c = d0 + n0w + nt*8 + 2*t;
                float b0v = bias[c], b1v = bias[c+1];
                *(uint32_t*)&out[(size_t)r*C_ + c] =
                    pk2((acc[z][mt][nt][0]+b0v)*scl, (acc[z][mt][nt][1]+b1v)*scl);
                *(uint32_t*)&out[(size_t)(r+8)*C_ + c] =
                    pk2((acc[z][mt][nt][2]+b0v)*scl, (acc[z][mt][nt][3]+b1v)*scl);
            }
        }
    }

    __syncthreads();
    {
        bf16* sT = smb;                 // [64][136] = 8704 elems < 12800
        #pragma unroll
        for (int mt = 0; mt < 2; mt++) {
            int r = m0w + mt*16 + g;
            #pragma unroll
            for (int nt = 0; nt < 4; nt++) {
                int c = n0w + nt*8 + 2*t;
                float b0v = bv[d0 + c], b1v = bv[d0 + c + 1];
                sT[c*136 + r]         = __float2bfloat16_rn(acc[2][mt][nt][0] + b0v);
                sT[(c+1)*136 + r]     = __float2bfloat16_rn(acc[2][mt][nt][1] + b1v);
                sT[c*136 + r + 8]     = __float2bfloat16_rn(acc[2][mt][nt][2] + b0v);
                sT[(c+1)*136 + r + 8] = __float2bfloat16_rn(acc[2][mt][nt][3] + b1v);
            }
        }
        __syncthreads();
        int bh = (m0 >> 10)*4 + (d0 >> 6);
        int tok0 = m0 & 1023;
        bf16* dst = g_vt + (size_t)bh*DH_*HW_;
        #pragma unroll
        for (int i = 0; i < 4; i++) {
            int idx = tid + i*256, d = idx>>4, ch = (idx&15)*8;
            *(uint4*)&dst[(size_t)d*HW_ + tok0 + ch] = *(uint4*)&sT[d*136 + ch];
        }
    }
}

// ---------------- Kernel 4: attention, 4 warps x 32 q-rows, cp.async ------
#define SQst 72
// smem elems: Q 128*72=9216, K/V double buf: 4*64*72=18432 -> 27648 (55296 B)
__global__ __launch_bounds__(128,3) void attn_kernel()
{
    extern __shared__ bf16 smb[];
    bf16* sQ = smb;                          // [128][SQst]
    bf16* sK[2] = { smb +  9216, smb + 18432 };
    bf16* sV[2] = { smb + 13824, smb + 23040 };
    int q0 = blockIdx.x*128;
    int bh = blockIdx.y, b = bh>>2, h = bh&3;
    size_t base = (size_t)b*HW_*C_ + (size_t)h*DH_;
    const bf16* vtb = g_vt + (size_t)bh*DH_*HW_;
    int tid = threadIdx.x, wid = tid>>5, lane = tid&31;

    int r8 = lane&7, mlo = (lane>>3)&1, mhi = lane>>4;
    uint32_t qB = su32(sQ) + (uint32_t)((wid*32 + r8 + mlo*8)*SQst + mhi*8)*2;
    uint32_t kB[2], vB[2];
    #pragma unroll
    for (int i = 0; i < 2; i++) {
        kB[i] = su32(sK[i]) + (uint32_t)((r8 + mhi*8)*SQst + mlo*8)*2;
        vB[i] = su32(sV[i]) + (uint32_t)((r8 + mhi*8)*SQst + mlo*8)*2;
    }

    // stage Q (128x64 = 1024 uint4): 8 per thread
    #pragma unroll
    for (int i = 0; i < 8; i++) {
        int f = tid + i*128, row = f>>3, seg = (f&7)*8;
        *(uint4*)&sQ[row*SQst + seg] =
            *(const uint4*)&g_q[base + (size_t)(q0+row)*C_ + seg];
    }
    auto ldtile = [&](int kt, int bb){
        #pragma unroll
        for (int i = 0; i < 4; i++) {
            int f = tid + i*128, row = f>>3, seg = (f&7)*8;
            CPA16(su32(&sK[bb][row*SQst + seg]),
                  &g_k[base + (size_t)(kt*64 + row)*C_ + seg]);
            CPA16(su32(&sV[bb][row*SQst + seg]),
                  &vtb[(size_t)row*HW_ + kt*64 + seg]);
        }
    };
    ldtile(0, 0); CP_COMMIT();

    __syncthreads();
    uint32_t aQ[2][4][4];
    #pragma unroll
    for (int mt = 0; mt < 2; mt++)
        #pragma unroll
        for (int k4 = 0; k4 < 4; k4++)
            ldsm4(aQ[mt][k4][0], aQ[mt][k4][1], aQ[mt][k4][2], aQ[mt][k4][3],
                  qB + (uint32_t)(mt*16*SQst + k4*16)*2);

    float o[2][8][4];
    #pragma unroll
    for (int mt = 0; mt < 2; mt++)
        #pragma unroll
        for (int nt = 0; nt < 8; nt++)
            #pragma unroll
            for (int i = 0; i < 4; i++) o[mt][nt][i] = 0.f;
    float lp[2][2] = {{0.f,0.f},{0.f,0.f}};

    for (int kt = 0; kt < 16; kt++) {
        int bb = kt & 1;
        CP_WAIT0();
        __syncthreads();
        if (kt < 15) { ldtile(kt+1, bb^1); CP_COMMIT(); }

        #pragma unroll
        for (int s = 0; s < 4; s++) {
            float S[2][2][4] = {};
            #pragma unroll
            for (int k4 = 0; k4 < 4; k4++) {
                uint32_t b0,b1,c0,c1;
                ldsm4(b0,b1,c0,c1, kB[bb] + (uint32_t)(s*16*SQst + k4*16)*2);
                #pragma unroll
                for (int mt = 0; mt < 2; mt++) {
                    mma16(S[mt][0], aQ[mt][k4][0],aQ[mt][k4][1],aQ[mt][k4][2],aQ[mt][k4][3], b0, b1);
                    mma16(S[mt][1], aQ[mt][k4][0],aQ[mt][k4][1],aQ[mt][k4][2],aQ[mt][k4][3], c0, c1);
                }
            }
            uint32_t p[2][4];
            #pragma unroll
            for (int mt = 0; mt < 2; mt++) {
                float e00 = __expf(S[mt][0][0]), e01 = __expf(S[mt][0][1]);
                float e02 = __expf(S[mt][0][2]), e03 = __expf(S[mt][0][3]);
                float e10 = __expf(S[mt][1][0]), e11 = __expf(S[mt][1][1]);
                float e12 = __expf(S[mt][1][2]), e13 = __expf(S[mt][1][3]);
                lp[mt][0] += e00 + e01 + e10 + e11;
                lp[mt][1] += e02 + e03 + e12 + e13;
                p[mt][0] = pk2(e00, e01);
                p[mt][1] = pk2(e02, e03);
                p[mt][2] = pk2(e10, e11);
                p[mt][3] = pk2(e12, e13);
            }
            #pragma unroll
            for (int nt2 = 0; nt2 < 4; nt2++) {
                uint32_t b0,b1,c0,c1;
                ldsm4(b0,b1,c0,c1, vB[bb] + (uint32_t)(nt2*16*SQst + s*16)*2);
                #pragma unroll
                for (int mt = 0; mt < 2; mt++) {
                    mma16(o[mt][2*nt2],   p[mt][0],p[mt][1],p[mt][2],p[mt][3], b0, b1);
                    mma16(o[mt][2*nt2+1], p[mt][0],p[mt][1],p[mt][2],p[mt][3], c0, c1);
                }
            }
        }
    }

    int g = lane>>2, t = lane&3;
    #pragma unroll
    for (int mt = 0; mt < 2; mt++) {
        lp[mt][0] += __shfl_xor_sync(0xffffffffu, lp[mt][0], 1);
        lp[mt][0] += __shfl_xor_sync(0xffffffffu, lp[mt][0], 2);
        lp[mt][1] += __shfl_xor_sync(0xffffffffu, lp[mt][1], 1);
        lp[mt][1] += __shfl_xor_sync(0xffffffffu, lp[mt][1], 2);
        float inv0 = 1.f / lp[mt][0], inv1 = 1.f / lp[mt][1];
        int row = q0 + wid*32 + mt*16 + g;
        #pragma unroll
        for (int nt = 0; nt < 8; nt++) {
            int c = nt*8 + 2*t;
            *(uint32_t*)&g_h[base + (size_t)row*C_ + c] =
                pk2(o[mt][nt][0]*inv0, o[mt][nt][1]*inv0);
            *(uint32_t*)&g_h[base + (size_t)(row+8)*C_ + c] =
                pk2(o[mt][nt][2]*inv1, o[mt][nt][3]*inv1);
        }
    }
}

// ---------------- Kernel 5: proj + bias + residual (coalesced epilogue) ----
// smem: max(sA+sB = 15360 B, sOut 64*132*4 = 33792 B) -> 33792 B
__global__ __launch_bounds__(256) void proj_kernel(
    const float* __restrict__ bp, const float* __restrict__ x,
    float* __restrict__ out)
{
    extern __shared__ bf16 smb[];
    bf16* sA = smb;                 // [128][SAE]
    bf16* sB = sA + 128*SAE;        // [64][SBE]
    const bf16* WT = g_wt + (size_t)3*C_*C_;
    int d0 = blockIdx.x*64, m0 = blockIdx.y*128;
    int tid = threadIdx.x, wid = tid>>5, lane = tid&31;
    int g = lane>>2, t = lane&3;
    int m0w = (wid>>1)*32, n0w = (wid&1)*32;

    int r8 = lane&7, mlo = (lane>>3)&1, mhi = lane>>4;
    uint32_t aB = su32(sA) + (uint32_t)((m0w + r8 + mlo*8)*SAE + mhi*8)*2;
    uint32_t bB = su32(sB) + (uint32_t)((n0w + r8 + mhi*8)*SBE + mlo*8)*2;

    float acc[2][4][4];
    #pragma unroll
    for (int mt = 0; mt < 2; mt++)
        #pragma unroll
        for (int nt = 0; nt < 4; nt++)
            #pragma unroll
            for (int i = 0; i < 4; i++) acc[mt][nt][i] = 0.f;

    for (int kc = 0; kc < 8; kc++) {
        int k0 = kc*32;
        __syncthreads();
        #pragma unroll
        for (int i = 0; i < 2; i++) {
            int f = tid + i*256, row = f>>2, seg = (f&3)*8;
            *(uint4*)&sA[row*SAE + seg] =
                *(const uint4*)&g_h[(size_t)(m0+row)*C_ + k0 + seg];
        }
        {
            int n = tid>>2, seg = (tid&3)*8;
            *(uint4*)&sB[n*SBE + seg] =
                *(const uint4*)&WT[(size_t)(d0+n)*C_ + k0 + seg];
        }
        __syncthreads();
        #pragma unroll
        for (int s = 0; s < 2; s++) {
            uint32_t a[2][4];
            #pragma unroll
            for (int mt = 0; mt < 2; mt++)
                ldsm4(a[mt][0], a[mt][1], a[mt][2], a[mt][3],
                      aB + (uint32_t)(mt*16*SAE + s*16)*2);
            #pragma unroll
            for (int nt2 = 0; nt2 < 2; nt2++) {
                uint32_t b0,b1,c0,c1;
                ldsm4(b0,b1,c0,c1, bB + (uint32_t)(nt2*16*SBE + s*16)*2);
                #pragma unroll
                for (int mt = 0; mt < 2; mt++) {
                    mma16(acc[mt][2*nt2],   a[mt][0],a[mt][1],a[mt][2],a[mt][3], b0, b1);
                    mma16(acc[mt][2*nt2+1], a[mt][0],a[mt][1],a[mt][2],a[mt][3], c0, c1);
                }
            }
        }
    }

    // stage acc+bias into smem [d_local 64][tok_local 128] then coalesced out
    __syncthreads();
    float* sOut = (float*)smb;      // [64][132] (528B rows, 16B aligned)
    #pragma unroll
    for (int mt = 0; mt < 2; mt++) {
        #pragma unroll
        for (int rh = 0; rh < 2; rh++) {
            int rl = m0w + mt*16 + g + rh*8;
            #pragma unroll
            for (int nt = 0; nt < 4; nt++) {
                int dl = n0w + nt*8 + 2*t;
                sOut[dl*132 + rl]     = acc[mt][nt][rh*2+0] + bp[d0+dl];
                sOut[(dl+1)*132 + rl] = acc[mt][nt][rh*2+1] + bp[d0+dl+1];
            }
        }
    }
    __syncthreads();
    int btok = m0 >> 10, n0 = m0 & 1023;
    #pragma unroll
    for (int i = 0; i < 8; i++) {
        int idx = tid + i*256;
        int d = idx>>5, tq = (idx&31)*4;
        float4 v = *(float4*)&sOut[d*132 + tq];
        size_t gi = ((size_t)btok*C_ + d0 + d)*HW_ + n0 + tq;
        float4 xv = *(const float4*)&x[gi];
        v.x = (v.x + xv.x)*RS2_; v.y = (v.y + xv.y)*RS2_;
        v.z = (v.z + xv.z)*RS2_; v.w = (v.w + xv.w)*RS2_;
        *(float4*)&out[gi] = v;
    }
}

// ---------------------------------------------------------------------------
extern "C" void kernel_launch(void* const* d_in, const int* in_sizes, int n_in,
                              void* d_out, int out_size)
{
    const float* x   = (const float*)d_in[0];
    const float* gns = (const float*)d_in[1];
    const float* gnb = (const float*)d_in[2];
    const float* Wq  = (const float*)d_in[3];
    const float* bq  = (const float*)d_in[4];
    const float* Wk  = (const float*)d_in[5];
    const float* bk  = (const float*)d_in[6];
    const float* Wv  = (const float*)d_in[7];
    const float* bv  = (const float*)d_in[8];
    const float* Wp  = (const float*)d_in[9];
    const float* bp  = (const float*)d_in[10];
    float* out = (float*)d_out;

    const int smem_qkv  = (128*SAE + 3*64*SBE) * 2;   // 25600 B
    const int smem_attn = 27648 * 2;                  // 55296 B
    const int smem_proj = 64*132*4;                   // 33792 B

    cudaFuncSetAttribute(attn_kernel,
                         cudaFuncAttributeMaxDynamicSharedMemorySize, smem_attn);

    gn_kernel  <<<B_*GROUPS_, 256>>>(x, gns, gnb);
    wt_kernel  <<<dim3(8,8,4), dim3(32,8)>>>(Wq, Wk, Wv, Wp);
    qkv_kernel <<<dim3(4, 128), 256, smem_qkv>>>(bq, bk, bv);
    attn_kernel<<<dim3(8, 64), 128, smem_attn>>>();
    proj_kernel<<<dim3(4, 128), 256, smem_proj>>>(bp, x, out);
}

// round 15
// speedup vs baseline: 1.0672x; 1.0145x over previous
#include <cuda_runtime.h>
#include <cuda_bf16.h>
#include <cstdint>
#include <math.h>

#define B_   16
#define C_   256
#define HW_  1024
#define HEADS_ 4
#define DH_  64
#define GROUPS_ 32
#define CPG_ 8
#define EPS_ 1e-6f
#define RS2_ 0.70710678118654752440f
// log2(e)/16 : folds the exp->exp2 conversion into the q pre-scale
#define QSCALE_ 0.09016844005213062f

typedef __nv_bfloat16 bf16;

// ---------------- scratch ----------------
__device__ bf16 g_xn[B_*HW_*C_];
__device__ bf16 g_q [B_*HW_*C_];   // pre-scaled by log2e/16
__device__ bf16 g_k [B_*HW_*C_];
__device__ bf16 g_h [B_*HW_*C_];
__device__ bf16 g_wt[4*C_*C_];     // W^T: [z][cout][cin]
__device__ bf16 g_vt[B_*HEADS_*DH_*HW_]; // V^T per (b,h): [d][token]

// ---------------- helpers ----------------
__device__ __forceinline__ uint32_t pk2(float lo, float hi){
    uint32_t d;
    asm("cvt.rn.bf16x2.f32 %0, %1, %2;" : "=r"(d) : "f"(hi), "f"(lo));
    return d;
}
__device__ __forceinline__ float ex2(float x){
    float y; asm("ex2.approx.f32 %0, %1;" : "=f"(y) : "f"(x)); return y;
}
__device__ __forceinline__ void mma16(float* c, uint32_t a0, uint32_t a1,
                                      uint32_t a2, uint32_t a3,
                                      uint32_t b0, uint32_t b1){
    asm volatile("mma.sync.aligned.m16n8k16.row.col.f32.bf16.bf16.f32 "
        "{%0,%1,%2,%3}, {%4,%5,%6,%7}, {%8,%9}, {%0,%1,%2,%3};"
        : "+f"(c[0]), "+f"(c[1]), "+f"(c[2]), "+f"(c[3])
        : "r"(a0), "r"(a1), "r"(a2), "r"(a3), "r"(b0), "r"(b1));
}
__device__ __forceinline__ void ldsm4(uint32_t& r0, uint32_t& r1,
                                      uint32_t& r2, uint32_t& r3, uint32_t a){
    asm volatile("ldmatrix.sync.aligned.m8n8.x4.shared.b16 {%0,%1,%2,%3}, [%4];"
        : "=r"(r0), "=r"(r1), "=r"(r2), "=r"(r3) : "r"(a));
}
__device__ __forceinline__ uint32_t su32(const void* p){
    return (uint32_t)__cvta_generic_to_shared(p);
}
#define CPA16(s, g) asm volatile("cp.async.cg.shared.global [%0], [%1], 16;" :: "r"(s), "l"(g))
#define CP_COMMIT() asm volatile("cp.async.commit_group;" ::: "memory")
#define CP_WAIT0()  asm volatile("cp.async.wait_group 0;" ::: "memory")

// ---------------- Kernel 1: GroupNorm -> (B,N,C) bf16 ----------------
__global__ __launch_bounds__(256) void gn_kernel(
    const float* __restrict__ x, const float* __restrict__ sc,
    const float* __restrict__ bi)
{
    __shared__ float xs[CPG_*HW_];
    __shared__ float red[64];
    int b = blockIdx.x >> 5, g = blockIdx.x & 31;
    const float* base = x + (size_t)b*C_*HW_ + (size_t)g*CPG_*HW_;
    int tid = threadIdx.x;
    float s = 0.f, sq = 0.f;
    #pragma unroll 8
    for (int i = tid; i < CPG_*HW_; i += 256) {
        float v = base[i]; xs[i] = v; s += v; sq += v*v;
    }
    #pragma unroll
    for (int o = 16; o; o >>= 1) {
        s  += __shfl_xor_sync(0xffffffffu, s,  o);
        sq += __shfl_xor_sync(0xffffffffu, sq, o);
    }
    int w = tid >> 5;
    if ((tid & 31) == 0) { red[w] = s; red[32+w] = sq; }
    __syncthreads();
    if (tid < 32) {
        s  = (tid < 8) ? red[tid]    : 0.f;
        sq = (tid < 8) ? red[32+tid] : 0.f;
        #pragma unroll
        for (int o = 4; o; o >>= 1) {
            s  += __shfl_xor_sync(0xffffffffu, s,  o);
            sq += __shfl_xor_sync(0xffffffffu, sq, o);
        }
        if (tid == 0) { red[0] = s; red[1] = sq; }
    }
    __syncthreads();
    float mean = red[0] * (1.f/8192.f);
    float var  = red[1] * (1.f/8192.f) - mean*mean;
    float rinv = rsqrtf(var + EPS_);
    float scs[CPG_], bis[CPG_];
    #pragma unroll
    for (int c = 0; c < CPG_; c++) { scs[c] = sc[g*CPG_+c]; bis[c] = bi[g*CPG_+c]; }
    for (int n = tid; n < HW_; n += 256) {
        float buf[CPG_];
        #pragma unroll
        for (int c = 0; c < CPG_; c++)
            buf[c] = (xs[c*HW_+n] - mean)*rinv*scs[c] + bis[c];
        uint4 u;
        u.x = pk2(buf[0],buf[1]); u.y = pk2(buf[2],buf[3]);
        u.z = pk2(buf[4],buf[5]); u.w = pk2(buf[6],buf[7]);
        *(uint4*)&g_xn[((size_t)(b*HW_+n))*C_ + g*CPG_] = u;
    }
}

// ---------------- Kernel 2: weight transpose -> bf16 [cout][cin] ----------
__global__ void wt_kernel(const float* __restrict__ Wq, const float* __restrict__ Wk,
                          const float* __restrict__ Wv, const float* __restrict__ Wp)
{
    __shared__ float t[32][33];
    int z = blockIdx.z;
    const float* W = (z==0)?Wq:(z==1)?Wk:(z==2)?Wv:Wp;
    bf16* WT = g_wt + (size_t)z*C_*C_;
    int x0 = blockIdx.x*32, y0 = blockIdx.y*32;
    int tx = threadIdx.x, ty = threadIdx.y;
    #pragma unroll
    for (int i = 0; i < 4; i++)
        t[ty+8*i][tx] = W[(size_t)(y0+ty+8*i)*C_ + x0+tx];
    __syncthreads();
    #pragma unroll
    for (int i = 0; i < 4; i++)
        WT[(size_t)(x0+ty+8*i)*C_ + y0+tx] = __float2bfloat16_rn(t[tx][ty+8*i]);
}

// ---------------- Kernel 3: fused QKV + V-transpose epilogue ----------------
#define SAE 40
#define SBE 40
__global__ __launch_bounds__(256) void qkv_kernel(
    const float* __restrict__ bq, const float* __restrict__ bk,
    const float* __restrict__ bv)
{
    extern __shared__ bf16 smb[];
    bf16* sA  = smb;                    // [128][SAE]
    bf16* sB0 = sA  + 128*SAE;          // [64][SBE] x3
    bf16* sB1 = sB0 + 64*SBE;
    bf16* sB2 = sB1 + 64*SBE;
    int d0 = blockIdx.x*64, m0 = blockIdx.y*128;
    int tid = threadIdx.x, wid = tid>>5, lane = tid&31;
    int g = lane>>2, t = lane&3;
    int m0w = (wid>>1)*32, n0w = (wid&1)*32;

    int r8 = lane&7, mlo = (lane>>3)&1, mhi = lane>>4;
    uint32_t aB  = su32(sA)  + (uint32_t)((m0w + r8 + mlo*8)*SAE + mhi*8)*2;
    uint32_t bB0 = su32(sB0) + (uint32_t)((n0w + r8 + mhi*8)*SBE + mlo*8)*2;
    uint32_t bB1 = su32(sB1) + (uint32_t)((n0w + r8 + mhi*8)*SBE + mlo*8)*2;
    uint32_t bB2 = su32(sB2) + (uint32_t)((n0w + r8 + mhi*8)*SBE + mlo*8)*2;

    float acc[3][2][4][4];
    #pragma unroll
    for (int z = 0; z < 3; z++)
        #pragma unroll
        for (int mt = 0; mt < 2; mt++)
            #pragma unroll
            for (int nt = 0; nt < 4; nt++)
                #pragma unroll
                for (int i = 0; i < 4; i++) acc[z][mt][nt][i] = 0.f;

    for (int kc = 0; kc < 8; kc++) {
        int k0 = kc*32;
        __syncthreads();
        #pragma unroll
        for (int i = 0; i < 2; i++) {
            int f = tid + i*256;
            int row = f>>2, seg = (f&3)*8;
            *(uint4*)&sA[row*SAE + seg] =
                *(const uint4*)&g_xn[(size_t)(m0+row)*C_ + k0 + seg];
        }
        {
            int n = tid>>2, seg = (tid&3)*8;
            size_t off = (size_t)(d0+n)*C_ + k0 + seg;
            *(uint4*)&sB0[n*SBE + seg] = *(const uint4*)&g_wt[off];
            *(uint4*)&sB1[n*SBE + seg] = *(const uint4*)&g_wt[C_*C_ + off];
            *(uint4*)&sB2[n*SBE + seg] = *(const uint4*)&g_wt[2*C_*C_ + off];
        }
        __syncthreads();
        #pragma unroll
        for (int s = 0; s < 2; s++) {
            uint32_t a[2][4];
            #pragma unroll
            for (int mt = 0; mt < 2; mt++)
                ldsm4(a[mt][0], a[mt][1], a[mt][2], a[mt][3],
                      aB + (uint32_t)(mt*16*SAE + s*16)*2);
            #pragma unroll
            for (int z = 0; z < 3; z++) {
                uint32_t bb = (z==0)?bB0:(z==1)?bB1:bB2;
                #pragma unroll
                for (int nt2 = 0; nt2 < 2; nt2++) {
                    uint32_t b0,b1,c0,c1;
                    ldsm4(b0,b1,c0,c1, bb + (uint32_t)(nt2*16*SBE + s*16)*2);
                    #pragma unroll
                    for (int mt = 0; mt < 2; mt++) {
                        mma16(acc[z][mt][2*nt2],   a[mt][0],a[mt][1],a[mt][2],a[mt][3], b0, b1);
                        mma16(acc[z][mt][2*nt2+1], a[mt][0],a[mt][1],a[mt][2],a[mt][3], c0, c1);
                    }
                }
            }
        }
    }

    #pragma unroll
    for (int z = 0; z < 2; z++) {
        const float* bias = (z==0)?bq:bk;
        bf16* out = (z==0)?g_q:g_k;
        float scl = (z==0)?QSCALE_:1.f;
        #pragma unroll
        for (int mt = 0; mt < 2; mt++) {
            int r = m0 + m0w + mt*16 + g;
            #pragma unroll
            for (int nt = 0; nt < 4; nt++) {
                int c = d0 + n0w + nt*8 + 2*t;
                float b0v = bias[c], b1v = bias[c+1];
                *(uint32_t*)&out[(size_t)r*C_ + c] =
                    pk2((acc[z][mt][nt][0]+b0v)*scl, (acc[z][mt][nt][1]+b1v)*scl);
                *(uint32_t*)&out[(size_t)(r+8)*C_ + c] =
                    pk2((acc[z][mt][nt][2]+b0v)*scl, (acc[z][mt][nt][3]+b1v)*scl);
            }
        }
    }

    __syncthreads();
    {
        bf16* sT = smb;                 // [64][136]
        #pragma unroll
        for (int mt = 0; mt < 2; mt++) {
            int r = m0w + mt*16 + g;
            #pragma unroll
            for (int nt = 0; nt < 4; nt++) {
                int c = n0w + nt*8 + 2*t;
                float b0v = bv[d0 + c], b1v = bv[d0 + c + 1];
                sT[c*136 + r]         = __float2bfloat16_rn(acc[2][mt][nt][0] + b0v);
                sT[(c+1)*136 + r]     = __float2bfloat16_rn(acc[2][mt][nt][1] + b1v);
                sT[c*136 + r + 8]     = __float2bfloat16_rn(acc[2][mt][nt][2] + b0v);
                sT[(c+1)*136 + r + 8] = __float2bfloat16_rn(acc[2][mt][nt][3] + b1v);
            }
        }
        __syncthreads();
        int bh = (m0 >> 10)*4 + (d0 >> 6);
        int tok0 = m0 & 1023;
        bf16* dst = g_vt + (size_t)bh*DH_*HW_;
        #pragma unroll
        for (int i = 0; i < 4; i++) {
            int idx = tid + i*256, d = idx>>4, ch = (idx&15)*8;
            *(uint4*)&dst[(size_t)d*HW_ + tok0 + ch] = *(uint4*)&sT[d*136 + ch];
        }
    }
}

// ---------------- Kernel 4: attention, exp2-softmax, V-ldsm hoisted -------
#define SQst 72
// smem elems: Q 128*72=9216, K/V double buf: 4*64*72=18432 -> 27648 (55296 B)
__global__ __launch_bounds__(128,3) void attn_kernel()
{
    extern __shared__ bf16 smb[];
    bf16* sQ = smb;                          // [128][SQst]
    bf16* sK[2] = { smb +  9216, smb + 18432 };
    bf16* sV[2] = { smb + 13824, smb + 23040 };
    int q0 = blockIdx.x*128;
    int bh = blockIdx.y, b = bh>>2, h = bh&3;
    size_t base = (size_t)b*HW_*C_ + (size_t)h*DH_;
    const bf16* vtb = g_vt + (size_t)bh*DH_*HW_;
    int tid = threadIdx.x, wid = tid>>5, lane = tid&31;

    int r8 = lane&7, mlo = (lane>>3)&1, mhi = lane>>4;
    uint32_t qB = su32(sQ) + (uint32_t)((wid*32 + r8 + mlo*8)*SQst + mhi*8)*2;
    uint32_t kB[2], vB[2];
    #pragma unroll
    for (int i = 0; i < 2; i++) {
        kB[i] = su32(sK[i]) + (uint32_t)((r8 + mhi*8)*SQst + mlo*8)*2;
        vB[i] = su32(sV[i]) + (uint32_t)((r8 + mhi*8)*SQst + mlo*8)*2;
    }

    #pragma unroll
    for (int i = 0; i < 8; i++) {
        int f = tid + i*128, row = f>>3, seg = (f&7)*8;
        *(uint4*)&sQ[row*SQst + seg] =
            *(const uint4*)&g_q[base + (size_t)(q0+row)*C_ + seg];
    }
    auto ldtile = [&](int kt, int bb){
        #pragma unroll
        for (int i = 0; i < 4; i++) {
            int f = tid + i*128, row = f>>3, seg = (f&7)*8;
            CPA16(su32(&sK[bb][row*SQst + seg]),
                  &g_k[base + (size_t)(kt*64 + row)*C_ + seg]);
            CPA16(su32(&sV[bb][row*SQst + seg]),
                  &vtb[(size_t)row*HW_ + kt*64 + seg]);
        }
    };
    ldtile(0, 0); CP_COMMIT();

    __syncthreads();
    uint32_t aQ[2][4][4];
    #pragma unroll
    for (int mt = 0; mt < 2; mt++)
        #pragma unroll
        for (int k4 = 0; k4 < 4; k4++)
            ldsm4(aQ[mt][k4][0], aQ[mt][k4][1], aQ[mt][k4][2], aQ[mt][k4][3],
                  qB + (uint32_t)(mt*16*SQst + k4*16)*2);

    float o[2][8][4];
    #pragma unroll
    for (int mt = 0; mt < 2; mt++)
        #pragma unroll
        for (int nt = 0; nt < 8; nt++)
            #pragma unroll
            for (int i = 0; i < 4; i++) o[mt][nt][i] = 0.f;
    float lp[2][2] = {{0.f,0.f},{0.f,0.f}};

    for (int kt = 0; kt < 16; kt++) {
        int bb = kt & 1;
        CP_WAIT0();
        __syncthreads();
        if (kt < 15) { ldtile(kt+1, bb^1); CP_COMMIT(); }

        #pragma unroll
        for (int s = 0; s < 4; s++) {
            float S[2][2][4] = {};
            #pragma unroll
            for (int k4 = 0; k4 < 4; k4++) {
                uint32_t b0,b1,c0,c1;
                ldsm4(b0,b1,c0,c1, kB[bb] + (uint32_t)(s*16*SQst + k4*16)*2);
                #pragma unroll
                for (int mt = 0; mt < 2; mt++) {
                    mma16(S[mt][0], aQ[mt][k4][0],aQ[mt][k4][1],aQ[mt][k4][2],aQ[mt][k4][3], b0, b1);
                    mma16(S[mt][1], aQ[mt][k4][0],aQ[mt][k4][1],aQ[mt][k4][2],aQ[mt][k4][3], c0, c1);
                }
            }
            // hoist V fragment loads: independent of S, hide under exp chain
            uint32_t vb[4][4];
            #pragma unroll
            for (int nt2 = 0; nt2 < 4; nt2++)
                ldsm4(vb[nt2][0], vb[nt2][1], vb[nt2][2], vb[nt2][3],
                      vB[bb] + (uint32_t)(nt2*16*SQst + s*16)*2);
            uint32_t p[2][4];
            #pragma unroll
            for (int mt = 0; mt < 2; mt++) {
                float e00 = ex2(S[mt][0][0]), e01 = ex2(S[mt][0][1]);
                float e02 = ex2(S[mt][0][2]), e03 = ex2(S[mt][0][3]);
                float e10 = ex2(S[mt][1][0]), e11 = ex2(S[mt][1][1]);
                float e12 = ex2(S[mt][1][2]), e13 = ex2(S[mt][1][3]);
                lp[mt][0] += e00 + e01 + e10 + e11;
                lp[mt][1] += e02 + e03 + e12 + e13;
                p[mt][0] = pk2(e00, e01);
                p[mt][1] = pk2(e02, e03);
                p[mt][2] = pk2(e10, e11);
                p[mt][3] = pk2(e12, e13);
            }
            #pragma unroll
            for (int nt2 = 0; nt2 < 4; nt2++) {
                #pragma unroll
                for (int mt = 0; mt < 2; mt++) {
                    mma16(o[mt][2*nt2],   p[mt][0],p[mt][1],p[mt][2],p[mt][3],
                          vb[nt2][0], vb[nt2][1]);
                    mma16(o[mt][2*nt2+1], p[mt][0],p[mt][1],p[mt][2],p[mt][3],
                          vb[nt2][2], vb[nt2][3]);
                }
            }
        }
    }

    int g = lane>>2, t = lane&3;
    #pragma unroll
    for (int mt = 0; mt < 2; mt++) {
        lp[mt][0] += __shfl_xor_sync(0xffffffffu, lp[mt][0], 1);
        lp[mt][0] += __shfl_xor_sync(0xffffffffu, lp[mt][0], 2);
        lp[mt][1] += __shfl_xor_sync(0xffffffffu, lp[mt][1], 1);
        lp[mt][1] += __shfl_xor_sync(0xffffffffu, lp[mt][1], 2);
        float inv0 = 1.f / lp[mt][0], inv1 = 1.f / lp[mt][1];
        int row = q0 + wid*32 + mt*16 + g;
        #pragma unroll
        for (int nt = 0; nt < 8; nt++) {
            int c = nt*8 + 2*t;
            *(uint32_t*)&g_h[base + (size_t)row*C_ + c] =
                pk2(o[mt][nt][0]*inv0, o[mt][nt][1]*inv0);
            *(uint32_t*)&g_h[base + (size_t)(row+8)*C_ + c] =
                pk2(o[mt][nt][2]*inv1, o[mt][nt][3]*inv1);
        }
    }
}

// ---------------- Kernel 5: proj + bias + residual (coalesced epilogue) ----
__global__ __launch_bounds__(256) void proj_kernel(
    const float* __restrict__ bp, const float* __restrict__ x,
    float* __restrict__ out)
{
    extern __shared__ bf16 smb[];
    bf16* sA = smb;                 // [128][SAE]
    bf16* sB = sA + 128*SAE;        // [64][SBE]
    const bf16* WT = g_wt + (size_t)3*C_*C_;
    int d0 = blockIdx.x*64, m0 = blockIdx.y*128;
    int tid = threadIdx.x, wid = tid>>5, lane = tid&31;
    int g = lane>>2, t = lane&3;
    int m0w = (wid>>1)*32, n0w = (wid&1)*32;

    int r8 = lane&7, mlo = (lane>>3)&1, mhi = lane>>4;
    uint32_t aB = su32(sA) + (uint32_t)((m0w + r8 + mlo*8)*SAE + mhi*8)*2;
    uint32_t bB = su32(sB) + (uint32_t)((n0w + r8 + mhi*8)*SBE + mlo*8)*2;

    float acc[2][4][4];
    #pragma unroll
    for (int mt = 0; mt < 2; mt++)
        #pragma unroll
        for (int nt = 0; nt < 4; nt++)
            #pragma unroll
            for (int i = 0; i < 4; i++) acc[mt][nt][i] = 0.f;

    for (int kc = 0; kc < 8; kc++) {
        int k0 = kc*32;
        __syncthreads();
        #pragma unroll
        for (int i = 0; i < 2; i++) {
            int f = tid + i*256, row = f>>2, seg = (f&3)*8;
            *(uint4*)&sA[row*SAE + seg] =
                *(const uint4*)&g_h[(size_t)(m0+row)*C_ + k0 + seg];
        }
        {
            int n = tid>>2, seg = (tid&3)*8;
            *(uint4*)&sB[n*SBE + seg] =
                *(const uint4*)&WT[(size_t)(d0+n)*C_ + k0 + seg];
        }
        __syncthreads();
        #pragma unroll
        for (int s = 0; s < 2; s++) {
            uint32_t a[2][4];
            #pragma unroll
            for (int mt = 0; mt < 2; mt++)
                ldsm4(a[mt][0], a[mt][1], a[mt][2], a[mt][3],
                      aB + (uint32_t)(mt*16*SAE + s*16)*2);
            #pragma unroll
            for (int nt2 = 0; nt2 < 2; nt2++) {
                uint32_t b0,b1,c0,c1;
                ldsm4(b0,b1,c0,c1, bB + (uint32_t)(nt2*16*SBE + s*16)*2);
                #pragma unroll
                for (int mt = 0; mt < 2; mt++) {
                    mma16(acc[mt][2*nt2],   a[mt][0],a[mt][1],a[mt][2],a[mt][3], b0, b1);
                    mma16(acc[mt][2*nt2+1], a[mt][0],a[mt][1],a[mt][2],a[mt][3], c0, c1);
                }
            }
        }
    }

    __syncthreads();
    float* sOut = (float*)smb;      // [64][132]
    #pragma unroll
    for (int mt = 0; mt < 2; mt++) {
        #pragma unroll
        for (int rh = 0; rh < 2; rh++) {
            int rl = m0w + mt*16 + g + rh*8;
            #pragma unroll
            for (int nt = 0; nt < 4; nt++) {
                int dl = n0w + nt*8 + 2*t;
                sOut[dl*132 + rl]     = acc[mt][nt][rh*2+0] + bp[d0+dl];
                sOut[(dl+1)*132 + rl] = acc[mt][nt][rh*2+1] + bp[d0+dl+1];
            }
        }
    }
    __syncthreads();
    int btok = m0 >> 10, n0 = m0 & 1023;
    #pragma unroll
    for (int i = 0; i < 8; i++) {
        int idx = tid + i*256;
        int d = idx>>5, tq = (idx&31)*4;
        float4 v = *(float4*)&sOut[d*132 + tq];
        size_t gi = ((size_t)btok*C_ + d0 + d)*HW_ + n0 + tq;
        float4 xv = *(const float4*)&x[gi];
        v.x = (v.x + xv.x)*RS2_; v.y = (v.y + xv.y)*RS2_;
        v.z = (v.z + xv.z)*RS2_; v.w = (v.w + xv.w)*RS2_;
        *(float4*)&out[gi] = v;
    }
}

// ---------------------------------------------------------------------------
extern "C" void kernel_launch(void* const* d_in, const int* in_sizes, int n_in,
                              void* d_out, int out_size)
{
    const float* x   = (const float*)d_in[0];
    const float* gns = (const float*)d_in[1];
    const float* gnb = (const float*)d_in[2];
    const float* Wq  = (const float*)d_in[3];
    const float* bq  = (const float*)d_in[4];
    const float* Wk  = (const float*)d_in[5];
    const float* bk  = (const float*)d_in[6];
    const float* Wv  = (const float*)d_in[7];
    const float* bv  = (const float*)d_in[8];
    const float* Wp  = (const float*)d_in[9];
    const float* bp  = (const float*)d_in[10];
    float* out = (float*)d_out;

    const int smem_qkv  = (128*SAE + 3*64*SBE) * 2;   // 25600 B
    const int smem_attn = 27648 * 2;                  // 55296 B
    const int smem_proj = 64*132*4;                   // 33792 B

    cudaFuncSetAttribute(attn_kernel,
                         cudaFuncAttributeMaxDynamicSharedMemorySize, smem_attn);

    gn_kernel  <<<B_*GROUPS_, 256>>>(x, gns, gnb);
    wt_kernel  <<<dim3(8,8,4), dim3(32,8)>>>(Wq, Wk, Wv, Wp);
    qkv_kernel <<<dim3(4, 128), 256, smem_qkv>>>(bq, bk, bv);
    attn_kernel<<<dim3(8, 64), 128, smem_attn>>>();
    proj_kernel<<<dim3(4, 128), 256, smem_proj>>>(bp, x, out);
}

// round 16
// speedup vs baseline: 1.1033x; 1.0338x over previous
#include <cuda_runtime.h>
#include <cuda_bf16.h>
#include <cstdint>
#include <math.h>

#define B_   16
#define C_   256
#define HW_  1024
#define HEADS_ 4
#define DH_  64
#define GROUPS_ 32
#define CPG_ 8
#define EPS_ 1e-6f
#define RS2_ 0.70710678118654752440f
// log2(e)/16 : folds the exp->exp2 conversion into the q pre-scale
#define QSCALE_ 0.09016844005213062f

typedef __nv_bfloat16 bf16;

// ---------------- scratch ----------------
__device__ bf16 g_xn[B_*HW_*C_];
__device__ bf16 g_q [B_*HW_*C_];   // pre-scaled by log2e/16
__device__ bf16 g_k [B_*HW_*C_];
__device__ bf16 g_h [B_*HW_*C_];
__device__ bf16 g_wt[4*C_*C_];     // W^T: [z][cout][cin]
__device__ bf16 g_vt[B_*HEADS_*DH_*HW_]; // V^T per (b,h): [d][token]

// ---------------- helpers ----------------
__device__ __forceinline__ uint32_t pk2(float lo, float hi){
    uint32_t d;
    asm("cvt.rn.bf16x2.f32 %0, %1, %2;" : "=r"(d) : "f"(hi), "f"(lo));
    return d;
}
__device__ __forceinline__ float ex2(float x){
    float y; asm("ex2.approx.f32 %0, %1;" : "=f"(y) : "f"(x)); return y;
}
__device__ __forceinline__ void mma16(float* c, uint32_t a0, uint32_t a1,
                                      uint32_t a2, uint32_t a3,
                                      uint32_t b0, uint32_t b1){
    asm volatile("mma.sync.aligned.m16n8k16.row.col.f32.bf16.bf16.f32 "
        "{%0,%1,%2,%3}, {%4,%5,%6,%7}, {%8,%9}, {%0,%1,%2,%3};"
        : "+f"(c[0]), "+f"(c[1]), "+f"(c[2]), "+f"(c[3])
        : "r"(a0), "r"(a1), "r"(a2), "r"(a3), "r"(b0), "r"(b1));
}
__device__ __forceinline__ void ldsm4(uint32_t& r0, uint32_t& r1,
                                      uint32_t& r2, uint32_t& r3, uint32_t a){
    asm volatile("ldmatrix.sync.aligned.m8n8.x4.shared.b16 {%0,%1,%2,%3}, [%4];"
        : "=r"(r0), "=r"(r1), "=r"(r2), "=r"(r3) : "r"(a));
}
__device__ __forceinline__ uint32_t su32(const void* p){
    return (uint32_t)__cvta_generic_to_shared(p);
}
#define CPA16(s, g) asm volatile("cp.async.cg.shared.global [%0], [%1], 16;" :: "r"(s), "l"(g))
#define CP_COMMIT() asm volatile("cp.async.commit_group;" ::: "memory")
#define CP_WAIT0()  asm volatile("cp.async.wait_group 0;" ::: "memory")

// ---------------- Kernel 1: GroupNorm -> (B,N,C) bf16 ----------------
__global__ __launch_bounds__(256) void gn_kernel(
    const float* __restrict__ x, const float* __restrict__ sc,
    const float* __restrict__ bi)
{
    __shared__ float xs[CPG_*HW_];
    __shared__ float red[64];
    int b = blockIdx.x >> 5, g = blockIdx.x & 31;
    const float* base = x + (size_t)b*C_*HW_ + (size_t)g*CPG_*HW_;
    int tid = threadIdx.x;
    float s = 0.f, sq = 0.f;
    #pragma unroll 8
    for (int i = tid; i < CPG_*HW_; i += 256) {
        float v = base[i]; xs[i] = v; s += v; sq += v*v;
    }
    #pragma unroll
    for (int o = 16; o; o >>= 1) {
        s  += __shfl_xor_sync(0xffffffffu, s,  o);
        sq += __shfl_xor_sync(0xffffffffu, sq, o);
    }
    int w = tid >> 5;
    if ((tid & 31) == 0) { red[w] = s; red[32+w] = sq; }
    __syncthreads();
    if (tid < 32) {
        s  = (tid < 8) ? red[tid]    : 0.f;
        sq = (tid < 8) ? red[32+tid] : 0.f;
        #pragma unroll
        for (int o = 4; o; o >>= 1) {
            s  += __shfl_xor_sync(0xffffffffu, s,  o);
            sq += __shfl_xor_sync(0xffffffffu, sq, o);
        }
        if (tid == 0) { red[0] = s; red[1] = sq; }
    }
    __syncthreads();
    float mean = red[0] * (1.f/8192.f);
    float var  = red[1] * (1.f/8192.f) - mean*mean;
    float rinv = rsqrtf(var + EPS_);
    float scs[CPG_], bis[CPG_];
    #pragma unroll
    for (int c = 0; c < CPG_; c++) { scs[c] = sc[g*CPG_+c]; bis[c] = bi[g*CPG_+c]; }
    for (int n = tid; n < HW_; n += 256) {
        float buf[CPG_];
        #pragma unroll
        for (int c = 0; c < CPG_; c++)
            buf[c] = (xs[c*HW_+n] - mean)*rinv*scs[c] + bis[c];
        uint4 u;
        u.x = pk2(buf[0],buf[1]); u.y = pk2(buf[2],buf[3]);
        u.z = pk2(buf[4],buf[5]); u.w = pk2(buf[6],buf[7]);
        *(uint4*)&g_xn[((size_t)(b*HW_+n))*C_ + g*CPG_] = u;
    }
}

// ---------------- Kernel 2: weight transpose -> bf16 [cout][cin] ----------
__global__ void wt_kernel(const float* __restrict__ Wq, const float* __restrict__ Wk,
                          const float* __restrict__ Wv, const float* __restrict__ Wp)
{
    __shared__ float t[32][33];
    int z = blockIdx.z;
    const float* W = (z==0)?Wq:(z==1)?Wk:(z==2)?Wv:Wp;
    bf16* WT = g_wt + (size_t)z*C_*C_;
    int x0 = blockIdx.x*32, y0 = blockIdx.y*32;
    int tx = threadIdx.x, ty = threadIdx.y;
    #pragma unroll
    for (int i = 0; i < 4; i++)
        t[ty+8*i][tx] = W[(size_t)(y0+ty+8*i)*C_ + x0+tx];
    __syncthreads();
    #pragma unroll
    for (int i = 0; i < 4; i++)
        WT[(size_t)(x0+ty+8*i)*C_ + y0+tx] = __float2bfloat16_rn(t[tx][ty+8*i]);
}

// ---------------- Kernel 3: fused QKV + V-transpose, cp.async pipeline ----
#define SAE 40
#define SBE 40
// smem elems: A 2*128*40=10240, B 3*2*64*40=15360 -> 25600 (51200 B)
__global__ __launch_bounds__(256) void qkv_kernel(
    const float* __restrict__ bq, const float* __restrict__ bk,
    const float* __restrict__ bv)
{
    extern __shared__ bf16 smb[];
    bf16* sA = smb;                            // [2][128][SAE]
    bf16* sB = smb + 2*128*SAE;                // [3][2][64][SBE]
    const uint32_t ABUF = 128*SAE*2;           // byte offset between A buffers
    const uint32_t BBUF = 64*SBE*2;            // byte offset between B buffers
    int d0 = blockIdx.x*64, m0 = blockIdx.y*128;
    int tid = threadIdx.x, wid = tid>>5, lane = tid&31;
    int g = lane>>2, t = lane&3;
    int m0w = (wid>>1)*32, n0w = (wid&1)*32;

    int r8 = lane&7, mlo = (lane>>3)&1, mhi = lane>>4;
    uint32_t aB0 = su32(sA) + (uint32_t)((m0w + r8 + mlo*8)*SAE + mhi*8)*2;
    uint32_t bBz[3];
    #pragma unroll
    for (int z = 0; z < 3; z++)
        bBz[z] = su32(sB) + (uint32_t)(z*2*64*SBE)*2
               + (uint32_t)((n0w + r8 + mhi*8)*SBE + mlo*8)*2;

    float acc[3][2][4][4];
    #pragma unroll
    for (int z = 0; z < 3; z++)
        #pragma unroll
        for (int mt = 0; mt < 2; mt++)
            #pragma unroll
            for (int nt = 0; nt < 4; nt++)
                #pragma unroll
                for (int i = 0; i < 4; i++) acc[z][mt][nt][i] = 0.f;

    auto ldt = [&](int kc, int bb){
        int k0 = kc*32;
        #pragma unroll
        for (int i = 0; i < 2; i++) {
            int f = tid + i*256, row = f>>2, seg = (f&3)*8;
            CPA16(su32(&sA[bb*128*SAE + row*SAE + seg]),
                  &g_xn[(size_t)(m0+row)*C_ + k0 + seg]);
        }
        int n = tid>>2, seg = (tid&3)*8;
        size_t off = (size_t)(d0+n)*C_ + k0 + seg;
        CPA16(su32(&sB[(0*2+bb)*64*SBE + n*SBE + seg]), &g_wt[off]);
        CPA16(su32(&sB[(1*2+bb)*64*SBE + n*SBE + seg]), &g_wt[C_*C_ + off]);
        CPA16(su32(&sB[(2*2+bb)*64*SBE + n*SBE + seg]), &g_wt[2*C_*C_ + off]);
    };
    ldt(0, 0); CP_COMMIT();

    for (int kc = 0; kc < 8; kc++) {
        int bb = kc & 1;
        CP_WAIT0();
        __syncthreads();
        if (kc < 7) { ldt(kc+1, bb^1); CP_COMMIT(); }
        uint32_t aOff = bb ? ABUF : 0u;
        uint32_t bOff = bb ? BBUF : 0u;
        #pragma unroll
        for (int s = 0; s < 2; s++) {
            uint32_t a[2][4];
            #pragma unroll
            for (int mt = 0; mt < 2; mt++)
                ldsm4(a[mt][0], a[mt][1], a[mt][2], a[mt][3],
                      aB0 + aOff + (uint32_t)(mt*16*SAE + s*16)*2);
            #pragma unroll
            for (int z = 0; z < 3; z++) {
                #pragma unroll
                for (int nt2 = 0; nt2 < 2; nt2++) {
                    uint32_t b0,b1,c0,c1;
                    ldsm4(b0,b1,c0,c1, bBz[z] + bOff + (uint32_t)(nt2*16*SBE + s*16)*2);
                    #pragma unroll
                    for (int mt = 0; mt < 2; mt++) {
                        mma16(acc[z][mt][2*nt2],   a[mt][0],a[mt][1],a[mt][2],a[mt][3], b0, b1);
                        mma16(acc[z][mt][2*nt2+1], a[mt][0],a[mt][1],a[mt][2],a[mt][3], c0, c1);
                    }
                }
            }
        }
    }

    #pragma unroll
    for (int z = 0; z < 2; z++) {
        const float* bias = (z==0)?bq:bk;
        bf16* out = (z==0)?g_q:g_k;
        float scl = (z==0)?QSCALE_:1.f;
        #pragma unroll
        for (int mt = 0; mt < 2; mt++) {
            int r = m0 + m0w + mt*16 + g;
            #pragma unroll
            for (int nt = 0; nt < 4; nt++) {
                int c = d0 + n0w + nt*8 + 2*t;
                float b0v = bias[c], b1v = bias[c+1];
                *(uint32_t*)&out[(size_t)r*C_ + c] =
                    pk2((acc[z][mt][nt][0]+b0v)*scl, (acc[z][mt][nt][1]+b1v)*scl);
                *(uint32_t*)&out[(size_t)(r+8)*C_ + c] =
                    pk2((acc[z][mt][nt][2]+b0v)*scl, (acc[z][mt][nt][3]+b1v)*scl);
            }
        }
    }

    __syncthreads();
    {
        bf16* sT = smb;                 // [64][136] = 8704 elems < 25600
        #pragma unroll
        for (int mt = 0; mt < 2; mt++) {
            int r = m0w + mt*16 + g;
            #pragma unroll
            for (int nt = 0; nt < 4; nt++) {
                int c = n0w + nt*8 + 2*t;
                float b0v = bv[d0 + c], b1v = bv[d0 + c + 1];
                sT[c*136 + r]         = __float2bfloat16_rn(acc[2][mt][nt][0] + b0v);
                sT[(c+1)*136 + r]     = __float2bfloat16_rn(acc[2][mt][nt][1] + b1v);
                sT[c*136 + r + 8]     = __float2bfloat16_rn(acc[2][mt][nt][2] + b0v);
                sT[(c+1)*136 + r + 8] = __float2bfloat16_rn(acc[2][mt][nt][3] + b1v);
            }
        }
        __syncthreads();
        int bh = (m0 >> 10)*4 + (d0 >> 6);
        int tok0 = m0 & 1023;
        bf16* dst = g_vt + (size_t)bh*DH_*HW_;
        #pragma unroll
        for (int i = 0; i < 4; i++) {
            int idx = tid + i*256, d = idx>>4, ch = (idx&15)*8;
            *(uint4*)&dst[(size_t)d*HW_ + tok0 + ch] = *(uint4*)&sT[d*136 + ch];
        }
    }
}

// ---------------- Kernel 4: attention, exp2-softmax, V-ldsm hoisted -------
#define SQst 72
__global__ __launch_bounds__(128,3) void attn_kernel()
{
    extern __shared__ bf16 smb[];
    bf16* sQ = smb;                          // [128][SQst]
    bf16* sK[2] = { smb +  9216, smb + 18432 };
    bf16* sV[2] = { smb + 13824, smb + 23040 };
    int q0 = blockIdx.x*128;
    int bh = blockIdx.y, b = bh>>2, h = bh&3;
    size_t base = (size_t)b*HW_*C_ + (size_t)h*DH_;
    const bf16* vtb = g_vt + (size_t)bh*DH_*HW_;
    int tid = threadIdx.x, wid = tid>>5, lane = tid&31;

    int r8 = lane&7, mlo = (lane>>3)&1, mhi = lane>>4;
    uint32_t qB = su32(sQ) + (uint32_t)((wid*32 + r8 + mlo*8)*SQst + mhi*8)*2;
    uint32_t kB[2], vB[2];
    #pragma unroll
    for (int i = 0; i < 2; i++) {
        kB[i] = su32(sK[i]) + (uint32_t)((r8 + mhi*8)*SQst + mlo*8)*2;
        vB[i] = su32(sV[i]) + (uint32_t)((r8 + mhi*8)*SQst + mlo*8)*2;
    }

    #pragma unroll
    for (int i = 0; i < 8; i++) {
        int f = tid + i*128, row = f>>3, seg = (f&7)*8;
        *(uint4*)&sQ[row*SQst + seg] =
            *(const uint4*)&g_q[base + (size_t)(q0+row)*C_ + seg];
    }
    auto ldtile = [&](int kt, int bb){
        #pragma unroll
        for (int i = 0; i < 4; i++) {
            int f = tid + i*128, row = f>>3, seg = (f&7)*8;
            CPA16(su32(&sK[bb][row*SQst + seg]),
                  &g_k[base + (size_t)(kt*64 + row)*C_ + seg]);
            CPA16(su32(&sV[bb][row*SQst + seg]),
                  &vtb[(size_t)row*HW_ + kt*64 + seg]);
        }
    };
    ldtile(0, 0); CP_COMMIT();

    __syncthreads();
    uint32_t aQ[2][4][4];
    #pragma unroll
    for (int mt = 0; mt < 2; mt++)
        #pragma unroll
        for (int k4 = 0; k4 < 4; k4++)
            ldsm4(aQ[mt][k4][0], aQ[mt][k4][1], aQ[mt][k4][2], aQ[mt][k4][3],
                  qB + (uint32_t)(mt*16*SQst + k4*16)*2);

    float o[2][8][4];
    #pragma unroll
    for (int mt = 0; mt < 2; mt++)
        #pragma unroll
        for (int nt = 0; nt < 8; nt++)
            #pragma unroll
            for (int i = 0; i < 4; i++) o[mt][nt][i] = 0.f;
    float lp[2][2] = {{0.f,0.f},{0.f,0.f}};

    for (int kt = 0; kt < 16; kt++) {
        int bb = kt & 1;
        CP_WAIT0();
        __syncthreads();
        if (kt < 15) { ldtile(kt+1, bb^1); CP_COMMIT(); }

        #pragma unroll
        for (int s = 0; s < 4; s++) {
            float S[2][2][4] = {};
            #pragma unroll
            for (int k4 = 0; k4 < 4; k4++) {
                uint32_t b0,b1,c0,c1;
                ldsm4(b0,b1,c0,c1, kB[bb] + (uint32_t)(s*16*SQst + k4*16)*2);
                #pragma unroll
                for (int mt = 0; mt < 2; mt++) {
                    mma16(S[mt][0], aQ[mt][k4][0],aQ[mt][k4][1],aQ[mt][k4][2],aQ[mt][k4][3], b0, b1);
                    mma16(S[mt][1], aQ[mt][k4][0],aQ[mt][k4][1],aQ[mt][k4][2],aQ[mt][k4][3], c0, c1);
                }
            }
            uint32_t vb[4][4];
            #pragma unroll
            for (int nt2 = 0; nt2 < 4; nt2++)
                ldsm4(vb[nt2][0], vb[nt2][1], vb[nt2][2], vb[nt2][3],
                      vB[bb] + (uint32_t)(nt2*16*SQst + s*16)*2);
            uint32_t p[2][4];
            #pragma unroll
            for (int mt = 0; mt < 2; mt++) {
                float e00 = ex2(S[mt][0][0]), e01 = ex2(S[mt][0][1]);
                float e02 = ex2(S[mt][0][2]), e03 = ex2(S[mt][0][3]);
                float e10 = ex2(S[mt][1][0]), e11 = ex2(S[mt][1][1]);
                float e12 = ex2(S[mt][1][2]), e13 = ex2(S[mt][1][3]);
                lp[mt][0] += e00 + e01 + e10 + e11;
                lp[mt][1] += e02 + e03 + e12 + e13;
                p[mt][0] = pk2(e00, e01);
                p[mt][1] = pk2(e02, e03);
                p[mt][2] = pk2(e10, e11);
                p[mt][3] = pk2(e12, e13);
            }
            #pragma unroll
            for (int nt2 = 0; nt2 < 4; nt2++) {
                #pragma unroll
                for (int mt = 0; mt < 2; mt++) {
                    mma16(o[mt][2*nt2],   p[mt][0],p[mt][1],p[mt][2],p[mt][3],
                          vb[nt2][0], vb[nt2][1]);
                    mma16(o[mt][2*nt2+1], p[mt][0],p[mt][1],p[mt][2],p[mt][3],
                          vb[nt2][2], vb[nt2][3]);
                }
            }
        }
    }

    int g = lane>>2, t = lane&3;
    #pragma unroll
    for (int mt = 0; mt < 2; mt++) {
        lp[mt][0] += __shfl_xor_sync(0xffffffffu, lp[mt][0], 1);
        lp[mt][0] += __shfl_xor_sync(0xffffffffu, lp[mt][0], 2);
        lp[mt][1] += __shfl_xor_sync(0xffffffffu, lp[mt][1], 1);
        lp[mt][1] += __shfl_xor_sync(0xffffffffu, lp[mt][1], 2);
        float inv0 = 1.f / lp[mt][0], inv1 = 1.f / lp[mt][1];
        int row = q0 + wid*32 + mt*16 + g;
        #pragma unroll
        for (int nt = 0; nt < 8; nt++) {
            int c = nt*8 + 2*t;
            *(uint32_t*)&g_h[base + (size_t)row*C_ + c] =
                pk2(o[mt][nt][0]*inv0, o[mt][nt][1]*inv0);
            *(uint32_t*)&g_h[base + (size_t)(row+8)*C_ + c] =
                pk2(o[mt][nt][2]*inv1, o[mt][nt][3]*inv1);
        }
    }
}

// ---------------- Kernel 5: proj + bias + residual, cp.async pipeline -----
// smem: max(loops 2*(128*40+64*40)*2 = 30720 B, sOut 64*132*4 = 33792 B)
__global__ __launch_bounds__(256) void proj_kernel(
    const float* __restrict__ bp, const float* __restrict__ x,
    float* __restrict__ out)
{
    extern __shared__ bf16 smb[];
    bf16* sA = smb;                            // [2][128][SAE]
    bf16* sB = smb + 2*128*SAE;                // [2][64][SBE]
    const uint32_t ABUF = 128*SAE*2;
    const uint32_t BBUF = 64*SBE*2;
    const bf16* WT = g_wt + (size_t)3*C_*C_;
    int d0 = blockIdx.x*64, m0 = blockIdx.y*128;
    int tid = threadIdx.x, wid = tid>>5, lane = tid&31;
    int g = lane>>2, t = lane&3;
    int m0w = (wid>>1)*32, n0w = (wid&1)*32;

    int r8 = lane&7, mlo = (lane>>3)&1, mhi = lane>>4;
    uint32_t aB0 = su32(sA) + (uint32_t)((m0w + r8 + mlo*8)*SAE + mhi*8)*2;
    uint32_t bB0 = su32(sB) + (uint32_t)((n0w + r8 + mhi*8)*SBE + mlo*8)*2;

    float acc[2][4][4];
    #pragma unroll
    for (int mt = 0; mt < 2; mt++)
        #pragma unroll
        for (int nt = 0; nt < 4; nt++)
            #pragma unroll
            for (int i = 0; i < 4; i++) acc[mt][nt][i] = 0.f;

    auto ldt = [&](int kc, int bb){
        int k0 = kc*32;
        #pragma unroll
        for (int i = 0; i < 2; i++) {
            int f = tid + i*256, row = f>>2, seg = (f&3)*8;
            CPA16(su32(&sA[bb*128*SAE + row*SAE + seg]),
                  &g_h[(size_t)(m0+row)*C_ + k0 + seg]);
        }
        int n = tid>>2, seg = (tid&3)*8;
        CPA16(su32(&sB[bb*64*SBE + n*SBE + seg]),
              &WT[(size_t)(d0+n)*C_ + k0 + seg]);
    };
    ldt(0, 0); CP_COMMIT();

    for (int kc = 0; kc < 8; kc++) {
        int bb = kc & 1;
        CP_WAIT0();
        __syncthreads();
        if (kc < 7) { ldt(kc+1, bb^1); CP_COMMIT(); }
        uint32_t aOff = bb ? ABUF : 0u;
        uint32_t bOff = bb ? BBUF : 0u;
        #pragma unroll
        for (int s = 0; s < 2; s++) {
            uint32_t a[2][4];
            #pragma unroll
            for (int mt = 0; mt < 2; mt++)
                ldsm4(a[mt][0], a[mt][1], a[mt][2], a[mt][3],
                      aB0 + aOff + (uint32_t)(mt*16*SAE + s*16)*2);
            #pragma unroll
            for (int nt2 = 0; nt2 < 2; nt2++) {
                uint32_t b0,b1,c0,c1;
                ldsm4(b0,b1,c0,c1, bB0 + bOff + (uint32_t)(nt2*16*SBE + s*16)*2);
                #pragma unroll
                for (int mt = 0; mt < 2; mt++) {
                    mma16(acc[mt][2*nt2],   a[mt][0],a[mt][1],a[mt][2],a[mt][3], b0, b1);
                    mma16(acc[mt][2*nt2+1], a[mt][0],a[mt][1],a[mt][2],a[mt][3], c0, c1);
                }
            }
        }
    }

    __syncthreads();
    float* sOut = (float*)smb;      // [64][132]
    #pragma unroll
    for (int mt = 0; mt < 2; mt++) {
        #pragma unroll
        for (int rh = 0; rh < 2; rh++) {
            int rl = m0w + mt*16 + g + rh*8;
            #pragma unroll
            for (int nt = 0; nt < 4; nt++) {
                int dl = n0w + nt*8 + 2*t;
                sOut[dl*132 + rl]     = acc[mt][nt][rh*2+0] + bp[d0+dl];
                sOut[(dl+1)*132 + rl] = acc[mt][nt][rh*2+1] + bp[d0+dl+1];
            }
        }
    }
    __syncthreads();
    int btok = m0 >> 10, n0 = m0 & 1023;
    #pragma unroll
    for (int i = 0; i < 8; i++) {
        int idx = tid + i*256;
        int d = idx>>5, tq = (idx&31)*4;
        float4 v = *(float4*)&sOut[d*132 + tq];
        size_t gi = ((size_t)btok*C_ + d0 + d)*HW_ + n0 + tq;
        float4 xv = *(const float4*)&x[gi];
        v.x = (v.x + xv.x)*RS2_; v.y = (v.y + xv.y)*RS2_;
        v.z = (v.z + xv.z)*RS2_; v.w = (v.w + xv.w)*RS2_;
        *(float4*)&out[gi] = v;
    }
}

// ---------------------------------------------------------------------------
extern "C" void kernel_launch(void* const* d_in, const int* in_sizes, int n_in,
                              void* d_out, int out_size)
{
    const float* x   = (const float*)d_in[0];
    const float* gns = (const float*)d_in[1];
    const float* gnb = (const float*)d_in[2];
    const float* Wq  = (const float*)d_in[3];
    const float* bq  = (const float*)d_in[4];
    const float* Wk  = (const float*)d_in[5];
    const float* bk  = (const float*)d_in[6];
    const float* Wv  = (const float*)d_in[7];
    const float* bv  = (const float*)d_in[8];
    const float* Wp  = (const float*)d_in[9];
    const float* bp  = (const float*)d_in[10];
    float* out = (float*)d_out;

    const int smem_qkv  = (2*128*SAE + 3*2*64*SBE) * 2;   // 51200 B
    const int smem_attn = 27648 * 2;                      // 55296 B
    const int smem_proj = 64*132*4;                       // 33792 B (covers 30720 loop use)

    cudaFuncSetAttribute(qkv_kernel,
                         cudaFuncAttributeMaxDynamicSharedMemorySize, smem_qkv);
    cudaFuncSetAttribute(attn_kernel,
                         cudaFuncAttributeMaxDynamicSharedMemorySize, smem_attn);

    gn_kernel  <<<B_*GROUPS_, 256>>>(x, gns, gnb);
    wt_kernel  <<<dim3(8,8,4), dim3(32,8)>>>(Wq, Wk, Wv, Wp);
    qkv_kernel <<<dim3(4, 128), 256, smem_qkv>>>(bq, bk, bv);
    attn_kernel<<<dim3(8, 64), 128, smem_attn>>>();
    proj_kernel<<<dim3(4, 128), 256, smem_proj>>>(bp, x, out);
}

// round 17
// speedup vs baseline: 1.1093x; 1.0054x over previous
#include <cuda_runtime.h>
#include <cuda_bf16.h>
#include <cstdint>
#include <math.h>

#define B_   16
#define C_   256
#define HW_  1024
#define HEADS_ 4
#define DH_  64
#define GROUPS_ 32
#define CPG_ 8
#define EPS_ 1e-6f
#define RS2_ 0.70710678118654752440f
// log2(e)/16 : folds the exp->exp2 conversion into the q pre-scale
#define QSCALE_ 0.09016844005213062f

typedef __nv_bfloat16 bf16;

// ---------------- scratch ----------------
__device__ bf16 g_xn[B_*HW_*C_];
__device__ bf16 g_q [B_*HW_*C_];   // pre-scaled by log2e/16
__device__ bf16 g_k [B_*HW_*C_];
__device__ bf16 g_h [B_*HW_*C_];
__device__ bf16 g_wt[4*C_*C_];     // W^T: [z][cout][cin]
__device__ bf16 g_vt[B_*HEADS_*DH_*HW_]; // V^T per (b,h): [d][token]

// ---------------- helpers ----------------
__device__ __forceinline__ uint32_t pk2(float lo, float hi){
    uint32_t d;
    asm("cvt.rn.bf16x2.f32 %0, %1, %2;" : "=r"(d) : "f"(hi), "f"(lo));
    return d;
}
__device__ __forceinline__ float ex2(float x){
    float y; asm("ex2.approx.f32 %0, %1;" : "=f"(y) : "f"(x)); return y;
}
__device__ __forceinline__ void mma16(float* c, uint32_t a0, uint32_t a1,
                                      uint32_t a2, uint32_t a3,
                                      uint32_t b0, uint32_t b1){
    asm volatile("mma.sync.aligned.m16n8k16.row.col.f32.bf16.bf16.f32 "
        "{%0,%1,%2,%3}, {%4,%5,%6,%7}, {%8,%9}, {%0,%1,%2,%3};"
        : "+f"(c[0]), "+f"(c[1]), "+f"(c[2]), "+f"(c[3])
        : "r"(a0), "r"(a1), "r"(a2), "r"(a3), "r"(b0), "r"(b1));
}
__device__ __forceinline__ void ldsm4(uint32_t& r0, uint32_t& r1,
                                      uint32_t& r2, uint32_t& r3, uint32_t a){
    asm volatile("ldmatrix.sync.aligned.m8n8.x4.shared.b16 {%0,%1,%2,%3}, [%4];"
        : "=r"(r0), "=r"(r1), "=r"(r2), "=r"(r3) : "r"(a));
}
__device__ __forceinline__ uint32_t su32(const void* p){
    return (uint32_t)__cvta_generic_to_shared(p);
}
#define CPA16(s, g) asm volatile("cp.async.cg.shared.global [%0], [%1], 16;" :: "r"(s), "l"(g))
#define CP_COMMIT() asm volatile("cp.async.commit_group;" ::: "memory")
#define CP_WAIT0()  asm volatile("cp.async.wait_group 0;" ::: "memory")

// ---------------- Kernel 1: GroupNorm -> (B,N,C) bf16 ----------------
__global__ __launch_bounds__(256) void gn_kernel(
    const float* __restrict__ x, const float* __restrict__ sc,
    const float* __restrict__ bi)
{
    __shared__ float xs[CPG_*HW_];
    __shared__ float red[64];
    int b = blockIdx.x >> 5, g = blockIdx.x & 31;
    const float* base = x + (size_t)b*C_*HW_ + (size_t)g*CPG_*HW_;
    int tid = threadIdx.x;
    float s = 0.f, sq = 0.f;
    #pragma unroll 8
    for (int i = tid; i < CPG_*HW_; i += 256) {
        float v = base[i]; xs[i] = v; s += v; sq += v*v;
    }
    #pragma unroll
    for (int o = 16; o; o >>= 1) {
        s  += __shfl_xor_sync(0xffffffffu, s,  o);
        sq += __shfl_xor_sync(0xffffffffu, sq, o);
    }
    int w = tid >> 5;
    if ((tid & 31) == 0) { red[w] = s; red[32+w] = sq; }
    __syncthreads();
    if (tid < 32) {
        s  = (tid < 8) ? red[tid]    : 0.f;
        sq = (tid < 8) ? red[32+tid] : 0.f;
        #pragma unroll
        for (int o = 4; o; o >>= 1) {
            s  += __shfl_xor_sync(0xffffffffu, s,  o);
            sq += __shfl_xor_sync(0xffffffffu, sq, o);
        }
        if (tid == 0) { red[0] = s; red[1] = sq; }
    }
    __syncthreads();
    float mean = red[0] * (1.f/8192.f);
    float var  = red[1] * (1.f/8192.f) - mean*mean;
    float rinv = rsqrtf(var + EPS_);
    float scs[CPG_], bis[CPG_];
    #pragma unroll
    for (int c = 0; c < CPG_; c++) { scs[c] = sc[g*CPG_+c]; bis[c] = bi[g*CPG_+c]; }
    for (int n = tid; n < HW_; n += 256) {
        float buf[CPG_];
        #pragma unroll
        for (int c = 0; c < CPG_; c++)
            buf[c] = (xs[c*HW_+n] - mean)*rinv*scs[c] + bis[c];
        uint4 u;
        u.x = pk2(buf[0],buf[1]); u.y = pk2(buf[2],buf[3]);
        u.z = pk2(buf[4],buf[5]); u.w = pk2(buf[6],buf[7]);
        *(uint4*)&g_xn[((size_t)(b*HW_+n))*C_ + g*CPG_] = u;
    }
}

// ---------------- Kernel 2: weight transpose -> bf16 [cout][cin] ----------
__global__ void wt_kernel(const float* __restrict__ Wq, const float* __restrict__ Wk,
                          const float* __restrict__ Wv, const float* __restrict__ Wp)
{
    __shared__ float t[32][33];
    int z = blockIdx.z;
    const float* W = (z==0)?Wq:(z==1)?Wk:(z==2)?Wv:Wp;
    bf16* WT = g_wt + (size_t)z*C_*C_;
    int x0 = blockIdx.x*32, y0 = blockIdx.y*32;
    int tx = threadIdx.x, ty = threadIdx.y;
    #pragma unroll
    for (int i = 0; i < 4; i++)
        t[ty+8*i][tx] = W[(size_t)(y0+ty+8*i)*C_ + x0+tx];
    __syncthreads();
    #pragma unroll
    for (int i = 0; i < 4; i++)
        WT[(size_t)(x0+ty+8*i)*C_ + y0+tx] = __float2bfloat16_rn(t[tx][ty+8*i]);
}

// ---------------- Kernel 3: fused QKV + V-transpose, cp.async pipeline ----
#define SAE 40
#define SBE 40
__global__ __launch_bounds__(256) void qkv_kernel(
    const float* __restrict__ bq, const float* __restrict__ bk,
    const float* __restrict__ bv)
{
    extern __shared__ bf16 smb[];
    bf16* sA = smb;                            // [2][128][SAE]
    bf16* sB = smb + 2*128*SAE;                // [3][2][64][SBE]
    const uint32_t ABUF = 128*SAE*2;
    const uint32_t BBUF = 64*SBE*2;
    int d0 = blockIdx.x*64, m0 = blockIdx.y*128;
    int tid = threadIdx.x, wid = tid>>5, lane = tid&31;
    int g = lane>>2, t = lane&3;
    int m0w = (wid>>1)*32, n0w = (wid&1)*32;

    int r8 = lane&7, mlo = (lane>>3)&1, mhi = lane>>4;
    uint32_t aB0 = su32(sA) + (uint32_t)((m0w + r8 + mlo*8)*SAE + mhi*8)*2;
    uint32_t bBz[3];
    #pragma unroll
    for (int z = 0; z < 3; z++)
        bBz[z] = su32(sB) + (uint32_t)(z*2*64*SBE)*2
               + (uint32_t)((n0w + r8 + mhi*8)*SBE + mlo*8)*2;

    float acc[3][2][4][4];
    #pragma unroll
    for (int z = 0; z < 3; z++)
        #pragma unroll
        for (int mt = 0; mt < 2; mt++)
            #pragma unroll
            for (int nt = 0; nt < 4; nt++)
                #pragma unroll
                for (int i = 0; i < 4; i++) acc[z][mt][nt][i] = 0.f;

    auto ldt = [&](int kc, int bb){
        int k0 = kc*32;
        #pragma unroll
        for (int i = 0; i < 2; i++) {
            int f = tid + i*256, row = f>>2, seg = (f&3)*8;
            CPA16(su32(&sA[bb*128*SAE + row*SAE + seg]),
                  &g_xn[(size_t)(m0+row)*C_ + k0 + seg]);
        }
        int n = tid>>2, seg = (tid&3)*8;
        size_t off = (size_t)(d0+n)*C_ + k0 + seg;
        CPA16(su32(&sB[(0*2+bb)*64*SBE + n*SBE + seg]), &g_wt[off]);
        CPA16(su32(&sB[(1*2+bb)*64*SBE + n*SBE + seg]), &g_wt[C_*C_ + off]);
        CPA16(su32(&sB[(2*2+bb)*64*SBE + n*SBE + seg]), &g_wt[2*C_*C_ + off]);
    };
    ldt(0, 0); CP_COMMIT();

    for (int kc = 0; kc < 8; kc++) {
        int bb = kc & 1;
        CP_WAIT0();
        __syncthreads();
        if (kc < 7) { ldt(kc+1, bb^1); CP_COMMIT(); }
        uint32_t aOff = bb ? ABUF : 0u;
        uint32_t bOff = bb ? BBUF : 0u;
        #pragma unroll
        for (int s = 0; s < 2; s++) {
            uint32_t a[2][4];
            #pragma unroll
            for (int mt = 0; mt < 2; mt++)
                ldsm4(a[mt][0], a[mt][1], a[mt][2], a[mt][3],
                      aB0 + aOff + (uint32_t)(mt*16*SAE + s*16)*2);
            #pragma unroll
            for (int z = 0; z < 3; z++) {
                #pragma unroll
                for (int nt2 = 0; nt2 < 2; nt2++) {
                    uint32_t b0,b1,c0,c1;
                    ldsm4(b0,b1,c0,c1, bBz[z] + bOff + (uint32_t)(nt2*16*SBE + s*16)*2);
                    #pragma unroll
                    for (int mt = 0; mt < 2; mt++) {
                        mma16(acc[z][mt][2*nt2],   a[mt][0],a[mt][1],a[mt][2],a[mt][3], b0, b1);
                        mma16(acc[z][mt][2*nt2+1], a[mt][0],a[mt][1],a[mt][2],a[mt][3], c0, c1);
                    }
                }
            }
        }
    }

    #pragma unroll
    for (int z = 0; z < 2; z++) {
        const float* bias = (z==0)?bq:bk;
        bf16* out = (z==0)?g_q:g_k;
        float scl = (z==0)?QSCALE_:1.f;
        #pragma unroll
        for (int mt = 0; mt < 2; mt++) {
            int r = m0 + m0w + mt*16 + g;
            #pragma unroll
            for (int nt = 0; nt < 4; nt++) {
                int c = d0 + n0w + nt*8 + 2*t;
                float b0v = bias[c], b1v = bias[c+1];
                *(uint32_t*)&out[(size_t)r*C_ + c] =
                    pk2((acc[z][mt][nt][0]+b0v)*scl, (acc[z][mt][nt][1]+b1v)*scl);
                *(uint32_t*)&out[(size_t)(r+8)*C_ + c] =
                    pk2((acc[z][mt][nt][2]+b0v)*scl, (acc[z][mt][nt][3]+b1v)*scl);
            }
        }
    }

    __syncthreads();
    {
        bf16* sT = smb;                 // [64][136]
        #pragma unroll
        for (int mt = 0; mt < 2; mt++) {
            int r = m0w + mt*16 + g;
            #pragma unroll
            for (int nt = 0; nt < 4; nt++) {
                int c = n0w + nt*8 + 2*t;
                float b0v = bv[d0 + c], b1v = bv[d0 + c + 1];
                sT[c*136 + r]         = __float2bfloat16_rn(acc[2][mt][nt][0] + b0v);
                sT[(c+1)*136 + r]     = __float2bfloat16_rn(acc[2][mt][nt][1] + b1v);
                sT[c*136 + r + 8]     = __float2bfloat16_rn(acc[2][mt][nt][2] + b0v);
                sT[(c+1)*136 + r + 8] = __float2bfloat16_rn(acc[2][mt][nt][3] + b1v);
            }
        }
        __syncthreads();
        int bh = (m0 >> 10)*4 + (d0 >> 6);
        int tok0 = m0 & 1023;
        bf16* dst = g_vt + (size_t)bh*DH_*HW_;
        #pragma unroll
        for (int i = 0; i < 4; i++) {
            int idx = tid + i*256, d = idx>>4, ch = (idx&15)*8;
            *(uint4*)&dst[(size_t)d*HW_ + tok0 + ch] = *(uint4*)&sT[d*136 + ch];
        }
    }
}

// ---------------- Kernel 4: attention, 4 CTAs/SM single wave --------------
#define SQst 72
__global__ __launch_bounds__(128,4) void attn_kernel()
{
    extern __shared__ bf16 smb[];
    bf16* sQ = smb;                          // [128][SQst]
    bf16* sK[2] = { smb +  9216, smb + 18432 };
    bf16* sV[2] = { smb + 13824, smb + 23040 };
    int q0 = blockIdx.x*128;
    int bh = blockIdx.y, b = bh>>2, h = bh&3;
    size_t base = (size_t)b*HW_*C_ + (size_t)h*DH_;
    const bf16* vtb = g_vt + (size_t)bh*DH_*HW_;
    int tid = threadIdx.x, wid = tid>>5, lane = tid&31;

    int r8 = lane&7, mlo = (lane>>3)&1, mhi = lane>>4;
    uint32_t qB = su32(sQ) + (uint32_t)((wid*32 + r8 + mlo*8)*SQst + mhi*8)*2;
    uint32_t kB[2], vB[2];
    #pragma unroll
    for (int i = 0; i < 2; i++) {
        kB[i] = su32(sK[i]) + (uint32_t)((r8 + mhi*8)*SQst + mlo*8)*2;
        vB[i] = su32(sV[i]) + (uint32_t)((r8 + mhi*8)*SQst + mlo*8)*2;
    }

    #pragma unroll
    for (int i = 0; i < 8; i++) {
        int f = tid + i*128, row = f>>3, seg = (f&7)*8;
        *(uint4*)&sQ[row*SQst + seg] =
            *(const uint4*)&g_q[base + (size_t)(q0+row)*C_ + seg];
    }
    auto ldtile = [&](int kt, int bb){
        #pragma unroll
        for (int i = 0; i < 4; i++) {
            int f = tid + i*128, row = f>>3, seg = (f&7)*8;
            CPA16(su32(&sK[bb][row*SQst + seg]),
                  &g_k[base + (size_t)(kt*64 + row)*C_ + seg]);
            CPA16(su32(&sV[bb][row*SQst + seg]),
                  &vtb[(size_t)row*HW_ + kt*64 + seg]);
        }
    };
    ldtile(0, 0); CP_COMMIT();

    __syncthreads();
    uint32_t aQ[2][4][4];
    #pragma unroll
    for (int mt = 0; mt < 2; mt++)
        #pragma unroll
        for (int k4 = 0; k4 < 4; k4++)
            ldsm4(aQ[mt][k4][0], aQ[mt][k4][1], aQ[mt][k4][2], aQ[mt][k4][3],
                  qB + (uint32_t)(mt*16*SQst + k4*16)*2);

    float o[2][8][4];
    #pragma unroll
    for (int mt = 0; mt < 2; mt++)
        #pragma unroll
        for (int nt = 0; nt < 8; nt++)
            #pragma unroll
            for (int i = 0; i < 4; i++) o[mt][nt][i] = 0.f;
    float lp[2][2] = {{0.f,0.f},{0.f,0.f}};

    for (int kt = 0; kt < 16; kt++) {
        int bb = kt & 1;
        CP_WAIT0();
        __syncthreads();
        if (kt < 15) { ldtile(kt+1, bb^1); CP_COMMIT(); }

        #pragma unroll
        for (int s = 0; s < 4; s++) {
            float S[2][2][4] = {};
            #pragma unroll
            for (int k4 = 0; k4 < 4; k4++) {
                uint32_t b0,b1,c0,c1;
                ldsm4(b0,b1,c0,c1, kB[bb] + (uint32_t)(s*16*SQst + k4*16)*2);
                #pragma unroll
                for (int mt = 0; mt < 2; mt++) {
                    mma16(S[mt][0], aQ[mt][k4][0],aQ[mt][k4][1],aQ[mt][k4][2],aQ[mt][k4][3], b0, b1);
                    mma16(S[mt][1], aQ[mt][k4][0],aQ[mt][k4][1],aQ[mt][k4][2],aQ[mt][k4][3], c0, c1);
                }
            }
            uint32_t p[2][4];
            #pragma unroll
            for (int mt = 0; mt < 2; mt++) {
                float e00 = ex2(S[mt][0][0]), e01 = ex2(S[mt][0][1]);
                float e02 = ex2(S[mt][0][2]), e03 = ex2(S[mt][0][3]);
                float e10 = ex2(S[mt][1][0]), e11 = ex2(S[mt][1][1]);
                float e12 = ex2(S[mt][1][2]), e13 = ex2(S[mt][1][3]);
                lp[mt][0] += e00 + e01 + e10 + e11;
                lp[mt][1] += e02 + e03 + e12 + e13;
                p[mt][0] = pk2(e00, e01);
                p[mt][1] = pk2(e02, e03);
                p[mt][2] = pk2(e10, e11);
                p[mt][3] = pk2(e12, e13);
            }
            #pragma unroll
            for (int nt2 = 0; nt2 < 4; nt2++) {
                uint32_t b0,b1,c0,c1;
                ldsm4(b0,b1,c0,c1, vB[bb] + (uint32_t)(nt2*16*SQst + s*16)*2);
                #pragma unroll
                for (int mt = 0; mt < 2; mt++) {
                    mma16(o[mt][2*nt2],   p[mt][0],p[mt][1],p[mt][2],p[mt][3], b0, b1);
                    mma16(o[mt][2*nt2+1], p[mt][0],p[mt][1],p[mt][2],p[mt][3], c0, c1);
                }
            }
        }
    }

    int g = lane>>2, t = lane&3;
    #pragma unroll
    for (int mt = 0; mt < 2; mt++) {
        lp[mt][0] += __shfl_xor_sync(0xffffffffu, lp[mt][0], 1);
        lp[mt][0] += __shfl_xor_sync(0xffffffffu, lp[mt][0], 2);
        lp[mt][1] += __shfl_xor_sync(0xffffffffu, lp[mt][1], 1);
        lp[mt][1] += __shfl_xor_sync(0xffffffffu, lp[mt][1], 2);
        float inv0 = 1.f / lp[mt][0], inv1 = 1.f / lp[mt][1];
        int row = q0 + wid*32 + mt*16 + g;
        #pragma unroll
        for (int nt = 0; nt < 8; nt++) {
            int c = nt*8 + 2*t;
            *(uint32_t*)&g_h[base + (size_t)row*C_ + c] =
                pk2(o[mt][nt][0]*inv0, o[mt][nt][1]*inv0);
            *(uint32_t*)&g_h[base + (size_t)(row+8)*C_ + c] =
                pk2(o[mt][nt][2]*inv1, o[mt][nt][3]*inv1);
        }
    }
}

// ---------------- Kernel 5: proj + bias + residual, cp.async pipeline -----
__global__ __launch_bounds__(256) void proj_kernel(
    const float* __restrict__ bp, const float* __restrict__ x,
    float* __restrict__ out)
{
    extern __shared__ bf16 smb[];
    bf16* sA = smb;                            // [2][128][SAE]
    bf16* sB = smb + 2*128*SAE;                // [2][64][SBE]
    const uint32_t ABUF = 128*SAE*2;
    const uint32_t BBUF = 64*SBE*2;
    const bf16* WT = g_wt + (size_t)3*C_*C_;
    int d0 = blockIdx.x*64, m0 = blockIdx.y*128;
    int tid = threadIdx.x, wid = tid>>5, lane = tid&31;
    int g = lane>>2, t = lane&3;
    int m0w = (wid>>1)*32, n0w = (wid&1)*32;

    int r8 = lane&7, mlo = (lane>>3)&1, mhi = lane>>4;
    uint32_t aB0 = su32(sA) + (uint32_t)((m0w + r8 + mlo*8)*SAE + mhi*8)*2;
    uint32_t bB0 = su32(sB) + (uint32_t)((n0w + r8 + mhi*8)*SBE + mlo*8)*2;

    float acc[2][4][4];
    #pragma unroll
    for (int mt = 0; mt < 2; mt++)
        #pragma unroll
        for (int nt = 0; nt < 4; nt++)
            #pragma unroll
            for (int i = 0; i < 4; i++) acc[mt][nt][i] = 0.f;

    auto ldt = [&](int kc, int bb){
        int k0 = kc*32;
        #pragma unroll
        for (int i = 0; i < 2; i++) {
            int f = tid + i*256, row = f>>2, seg = (f&3)*8;
            CPA16(su32(&sA[bb*128*SAE + row*SAE + seg]),
                  &g_h[(size_t)(m0+row)*C_ + k0 + seg]);
        }
        int n = tid>>2, seg = (tid&3)*8;
        CPA16(su32(&sB[bb*64*SBE + n*SBE + seg]),
              &WT[(size_t)(d0+n)*C_ + k0 + seg]);
    };
    ldt(0, 0); CP_COMMIT();

    for (int kc = 0; kc < 8; kc++) {
        int bb = kc & 1;
        CP_WAIT0();
        __syncthreads();
        if (kc < 7) { ldt(kc+1, bb^1); CP_COMMIT(); }
        uint32_t aOff = bb ? ABUF : 0u;
        uint32_t bOff = bb ? BBUF : 0u;
        #pragma unroll
        for (int s = 0; s < 2; s++) {
            uint32_t a[2][4];
            #pragma unroll
            for (int mt = 0; mt < 2; mt++)
                ldsm4(a[mt][0], a[mt][1], a[mt][2], a[mt][3],
                      aB0 + aOff + (uint32_t)(mt*16*SAE + s*16)*2);
            #pragma unroll
            for (int nt2 = 0; nt2 < 2; nt2++) {
                uint32_t b0,b1,c0,c1;
                ldsm4(b0,b1,c0,c1, bB0 + bOff + (uint32_t)(nt2*16*SBE + s*16)*2);
                #pragma unroll
                for (int mt = 0; mt < 2; mt++) {
                    mma16(acc[mt][2*nt2],   a[mt][0],a[mt][1],a[mt][2],a[mt][3], b0, b1);
                    mma16(acc[mt][2*nt2+1], a[mt][0],a[mt][1],a[mt][2],a[mt][3], c0, c1);
                }
            }
        }
    }

    __syncthreads();
    float* sOut = (float*)smb;      // [64][132]
    #pragma unroll
    for (int mt = 0; mt < 2; mt++) {
        #pragma unroll
        for (int rh = 0; rh < 2; rh++) {
            int rl = m0w + mt*16 + g + rh*8;
            #pragma unroll
            for (int nt = 0; nt < 4; nt++) {
                int dl = n0w + nt*8 + 2*t;
                sOut[dl*132 + rl]     = acc[mt][nt][rh*2+0] + bp[d0+dl];
                sOut[(dl+1)*132 + rl] = acc[mt][nt][rh*2+1] + bp[d0+dl+1];
            }
        }
    }
    __syncthreads();
    int btok = m0 >> 10, n0 = m0 & 1023;
    #pragma unroll
    for (int i = 0; i < 8; i++) {
        int idx = tid + i*256;
        int d = idx>>5, tq = (idx&31)*4;
        float4 v = *(float4*)&sOut[d*132 + tq];
        size_t gi = ((size_t)btok*C_ + d0 + d)*HW_ + n0 + tq;
        float4 xv = *(const float4*)&x[gi];
        v.x = (v.x + xv.x)*RS2_; v.y = (v.y + xv.y)*RS2_;
        v.z = (v.z + xv.z)*RS2_; v.w = (v.w + xv.w)*RS2_;
        *(float4*)&out[gi] = v;
    }
}

// ---------------------------------------------------------------------------
extern "C" void kernel_launch(void* const* d_in, const int* in_sizes, int n_in,
                              void* d_out, int out_size)
{
    const float* x   = (const float*)d_in[0];
    const float* gns = (const float*)d_in[1];
    const float* gnb = (const float*)d_in[2];
    const float* Wq  = (const float*)d_in[3];
    const float* bq  = (const float*)d_in[4];
    const float* Wk  = (const float*)d_in[5];
    const float* bk  = (const float*)d_in[6];
    const float* Wv  = (const float*)d_in[7];
    const float* bv  = (const float*)d_in[8];
    const float* Wp  = (const float*)d_in[9];
    const float* bp  = (const float*)d_in[10];
    float* out = (float*)d_out;

    const int smem_qkv  = (2*128*SAE + 3*2*64*SBE) * 2;   // 51200 B
    const int smem_attn = 27648 * 2;                      // 55296 B
    const int smem_proj = 64*132*4;                       // 33792 B

    cudaFuncSetAttribute(qkv_kernel,
                         cudaFuncAttributeMaxDynamicSharedMemorySize, smem_qkv);
    cudaFuncSetAttribute(attn_kernel,
                         cudaFuncAttributeMaxDynamicSharedMemorySize, smem_attn);

    gn_kernel  <<<B_*GROUPS_, 256>>>(x, gns, gnb);
    wt_kernel  <<<dim3(8,8,4), dim3(32,8)>>>(Wq, Wk, Wv, Wp);
    qkv_kernel <<<dim3(4, 128), 256, smem_qkv>>>(bq, bk, bv);
    attn_kernel<<<dim3(8, 64), 128, smem_attn>>>();
    proj_kernel<<<dim3(4, 128), 256, smem_proj>>>(bp, x, out);
}